// round 9
// baseline (speedup 1.0000x reference)
#include <cuda_runtime.h>

#define NN 500000
#define NE 1000000
#define NG 512

#define SCAN_BS 256
#define SCAN_ELEMS 2048                       // 256 threads * 8
#define SCAN_NBLK ((NN + SCAN_ELEMS - 1) / SCAN_ELEMS)   // 245

typedef unsigned long long u64;

// ---------------- scratch ----------------
__device__ int    g_cnt_out[NN];
__device__ int    g_cnt_in [NN];
__device__ float  g_ns     [NN];   // rsqrt(max(deg_out,1))
__device__ int    g_row_off[NN + 1];
__device__ int    g_cursor [NN];
__device__ int    g_csr_src[NE];
__device__ int    g_bsum [256];
__device__ int    g_bpref[256];
__device__ float4 g_h1[NN * 8];    // [N,32]
__device__ float4 g_hp[NN * 8];    // [N,32] relu(h1@Wpool+bpool)
__device__ float  g_probe_out[NG * 64];   // probe scratch (never read)

// ---------------- f32x2 helpers ----------------
__device__ __forceinline__ u64 pack2(float a) {
    u64 r;
    asm("mov.b64 %0, {%1, %1};" : "=l"(r) : "f"(a));
    return r;
}
__device__ __forceinline__ void fma2(u64& d, u64 a, u64 b) {
    asm("fma.rn.f32x2 %0, %1, %2, %0;" : "+l"(d) : "l"(a), "l"(b));
}
__device__ __forceinline__ float2 unpack2(u64 v) {
    float2 f;
    asm("mov.b64 {%0, %1}, %2;" : "=f"(f.x), "=f"(f.y) : "l"(v));
    return f;
}

// ---------------- init ----------------
__global__ void k_init(float* __restrict__ out) {
    int i = blockIdx.x * blockDim.x + threadIdx.x;
    if (i < NN) { g_cnt_out[i] = 0; g_cnt_in[i] = 0; }
    if (i < NG * 64) out[i] = 0.f;
}

// ---------------- degree counts ----------------
__global__ void k_deg(const int* __restrict__ src, const int* __restrict__ dst) {
    int e = blockIdx.x * blockDim.x + threadIdx.x;
    if (e < NE) {
        atomicAdd(&g_cnt_out[src[e]], 1);
        atomicAdd(&g_cnt_in [dst[e]], 1);
    }
}

// ---------------- scan pass 1 ----------------
__global__ __launch_bounds__(SCAN_BS) void k_scan_bsum() {
    __shared__ int sred[SCAN_BS];
    int b = blockIdx.x, t = threadIdx.x;
    int base = b * SCAN_ELEMS + t * 8;
    int s = 0;
#pragma unroll
    for (int k = 0; k < 8; k++) {
        int idx = base + k;
        if (idx < NN) s += g_cnt_in[idx];
    }
    sred[t] = s;
    __syncthreads();
    for (int o = SCAN_BS / 2; o > 0; o >>= 1) {
        if (t < o) sred[t] += sred[t + o];
        __syncthreads();
    }
    if (t == 0) g_bsum[b] = sred[0];
}

// ---------------- scan pass 2 ----------------
__global__ __launch_bounds__(SCAN_BS) void k_scan_top() {
    __shared__ int s[SCAN_BS];
    int t = threadIdx.x;
    int v = (t < SCAN_NBLK) ? g_bsum[t] : 0;
    s[t] = v;
    __syncthreads();
    for (int o = 1; o < SCAN_BS; o <<= 1) {
        int u = (t >= o) ? s[t - o] : 0;
        __syncthreads();
        s[t] += u;
        __syncthreads();
    }
    if (t < SCAN_NBLK) g_bpref[t] = s[t] - v;
    if (t == 0) g_row_off[NN] = NE;
}

// ---------------- scan pass 3 (also computes g_ns) ----------------
__global__ __launch_bounds__(SCAN_BS) void k_scan_write() {
    __shared__ int sth[SCAN_BS];
    int b = blockIdx.x, t = threadIdx.x;
    int base = b * SCAN_ELEMS + t * 8;
    int vals[8];
    int s = 0;
#pragma unroll
    for (int k = 0; k < 8; k++) {
        int idx = base + k;
        vals[k] = (idx < NN) ? g_cnt_in[idx] : 0;
        s += vals[k];
    }
    sth[t] = s;
    __syncthreads();
    int incl = s;
    for (int o = 1; o < SCAN_BS; o <<= 1) {
        int u = (t >= o) ? sth[t - o] : 0;
        __syncthreads();
        incl += u;
        sth[t] = incl;
        __syncthreads();
    }
    int run = g_bpref[b] + incl - s;
#pragma unroll
    for (int k = 0; k < 8; k++) {
        int idx = base + k;
        if (idx < NN) {
            g_row_off[idx] = run;
            g_cursor[idx] = run;
            g_ns[idx] = rsqrtf(fmaxf((float)g_cnt_out[idx], 1.0f));
        }
        run += vals[k];
    }
}

// ---------------- CSR fill ----------------
__global__ void k_fill(const int* __restrict__ src, const int* __restrict__ dst) {
    int e = blockIdx.x * blockDim.x + threadIdx.x;
    if (e < NE) {
        int p = atomicAdd(&g_cursor[dst[e]], 1);
        g_csr_src[p] = src[e];
    }
}

// ---------------- gather embed directly + MLP1 + pool MLP ----------------
__global__ __launch_bounds__(256) void k_h1(
    const int* __restrict__ tokens, const float* __restrict__ embed,
    const float* __restrict__ W1, const float* __restrict__ b1,
    const float* __restrict__ Wp, const float* __restrict__ bp)
{
    __shared__ __align__(16) u64 sW1[16 * 16], sWp[32 * 16];
    __shared__ u64 sb1[16], sbp[16];
    for (int t = threadIdx.x; t < 16 * 16; t += blockDim.x)
        ((float2*)sW1)[t] = ((const float2*)W1)[t];
    for (int t = threadIdx.x; t < 32 * 16; t += blockDim.x)
        ((float2*)sWp)[t] = ((const float2*)Wp)[t];
    for (int t = threadIdx.x; t < 16; t += blockDim.x) {
        ((float2*)sb1)[t] = ((const float2*)b1)[t];
        ((float2*)sbp)[t] = ((const float2*)bp)[t];
    }
    __syncthreads();

    int i = blockIdx.x * blockDim.x + threadIdx.x;
    if (i >= NN) return;

    int beg = g_row_off[i], end = g_row_off[i + 1];
    float4 a0 = make_float4(0, 0, 0, 0), a1 = a0, a2 = a0, a3 = a0;
    for (int e = beg; e < end; e++) {
        int s = g_csr_src[e];
        float ns = g_ns[s];
        const float4* er = (const float4*)(embed + (long)tokens[s] * 16);
        float4 v0 = er[0], v1 = er[1], v2 = er[2], v3 = er[3];
        a0.x += v0.x * ns; a0.y += v0.y * ns; a0.z += v0.z * ns; a0.w += v0.w * ns;
        a1.x += v1.x * ns; a1.y += v1.y * ns; a1.z += v1.z * ns; a1.w += v1.w * ns;
        a2.x += v2.x * ns; a2.y += v2.y * ns; a2.z += v2.z * ns; a2.w += v2.w * ns;
        a3.x += v3.x * ns; a3.y += v3.y * ns; a3.z += v3.z * ns; a3.w += v3.w * ns;
    }
    float nd = rsqrtf(fmaxf((float)(end - beg), 1.0f));
    float mr[16] = {a0.x * nd, a0.y * nd, a0.z * nd, a0.w * nd,
                    a1.x * nd, a1.y * nd, a1.z * nd, a1.w * nd,
                    a2.x * nd, a2.y * nd, a2.z * nd, a2.w * nd,
                    a3.x * nd, a3.y * nd, a3.z * nd, a3.w * nd};

    // h1 = relu(mr @ W1 + b1)
    u64 acc[16];
#pragma unroll
    for (int j = 0; j < 16; j++) acc[j] = sb1[j];
#pragma unroll
    for (int k = 0; k < 16; k++) {
        u64 av = pack2(mr[k]);
        const ulonglong2* pw = (const ulonglong2*)&sW1[k * 16];
#pragma unroll
        for (int jj = 0; jj < 8; jj++) {
            ulonglong2 w = pw[jj];
            fma2(acc[2 * jj], av, w.x);
            fma2(acc[2 * jj + 1], av, w.y);
        }
    }
    float h1f[32];
#pragma unroll
    for (int j = 0; j < 16; j++) {
        float2 f = unpack2(acc[j]);
        h1f[2 * j] = fmaxf(f.x, 0.f); h1f[2 * j + 1] = fmaxf(f.y, 0.f);
    }
#pragma unroll
    for (int k = 0; k < 8; k++)
        g_h1[i * 8 + k] = make_float4(h1f[4 * k], h1f[4 * k + 1], h1f[4 * k + 2], h1f[4 * k + 3]);

    // hp = relu(h1 @ Wpool + bpool)
    u64 pcc[16];
#pragma unroll
    for (int j = 0; j < 16; j++) pcc[j] = sbp[j];
#pragma unroll
    for (int k = 0; k < 32; k++) {
        u64 av = pack2(h1f[k]);
        const ulonglong2* pw = (const ulonglong2*)&sWp[k * 16];
#pragma unroll
        for (int jj = 0; jj < 8; jj++) {
            ulonglong2 w = pw[jj];
            fma2(pcc[2 * jj], av, w.x);
            fma2(pcc[2 * jj + 1], av, w.y);
        }
    }
#pragma unroll
    for (int j = 0; j < 8; j++) {
        float2 f0 = unpack2(pcc[2 * j]), f1 = unpack2(pcc[2 * j + 1]);
        g_hp[i * 8 + j] = make_float4(fmaxf(f0.x, 0.f), fmaxf(f0.y, 0.f),
                                      fmaxf(f1.x, 0.f), fmaxf(f1.y, 0.f));
    }
}

// ---------------- fused: gather-max + SAGE + lin + pooling ----------------
// 128 threads/block, 2 nodes/thread (slots tid and tid+128): each weight
// LDS.128 feeds 4 fma2 -> halves LSU pressure per FMA vs 1 node/thread.
// staging layout: stag[channel * 256 + slot], channels 0..63.
__device__ __forceinline__ void out_body(
    const int* __restrict__ graph_ids,
    const float* __restrict__ Wself, const float* __restrict__ Wneigh,
    const float* __restrict__ bneigh,
    const float* __restrict__ Wlin, const float* __restrict__ blin,
    float* __restrict__ out)
{
    __shared__ __align__(16) u64 sWs[32 * 32], sWn[32 * 32], sWl[64 * 32];
    __shared__ u64 sbn[32], sbl[32];
    extern __shared__ float stag[];   // 64 * 256 floats = 64KB dynamic

    for (int t = threadIdx.x; t < 32 * 32; t += blockDim.x) {
        ((float2*)sWs)[t] = ((const float2*)Wself)[t];
        ((float2*)sWn)[t] = ((const float2*)Wneigh)[t];
    }
    for (int t = threadIdx.x; t < 64 * 32; t += blockDim.x)
        ((float2*)sWl)[t] = ((const float2*)Wlin)[t];
    for (int t = threadIdx.x; t < 32; t += blockDim.x) {
        ((float2*)sbn)[t] = ((const float2*)bneigh)[t];
        ((float2*)sbl)[t] = ((const float2*)blin)[t];
    }
    __syncthreads();

    int tid = threadIdx.x;          // 0..127
    int base = blockIdx.x * 256;
    int i0 = base + tid, i1 = base + 128 + tid;
    bool valid0 = i0 < NN, valid1 = i1 < NN;
    int ic0 = valid0 ? i0 : NN - 1;
    int ic1 = valid1 ? i1 : NN - 1;
    int gid0 = graph_ids[ic0];
    int gid1 = graph_ids[ic1];

    // stage h1 rows + gather-max rows for both nodes
#pragma unroll
    for (int n = 0; n < 2; n++) {
        int ic = n ? ic1 : ic0;
        int slot = tid + n * 128;
#pragma unroll
        for (int k = 0; k < 8; k++) {
            float4 v = g_h1[(size_t)ic * 8 + k];
            stag[(4 * k + 0) * 256 + slot] = v.x;
            stag[(4 * k + 1) * 256 + slot] = v.y;
            stag[(4 * k + 2) * 256 + slot] = v.z;
            stag[(4 * k + 3) * 256 + slot] = v.w;
        }
        float hnf[32];
#pragma unroll
        for (int j = 0; j < 32; j++) hnf[j] = 0.f;
        int beg = g_row_off[ic], end = g_row_off[ic + 1];
        for (int e = beg; e < end; e++) {
            const float4* hr = &g_hp[(size_t)g_csr_src[e] * 8];
#pragma unroll
            for (int k = 0; k < 8; k++) {
                float4 v = hr[k];
                hnf[4 * k + 0] = fmaxf(hnf[4 * k + 0], v.x);
                hnf[4 * k + 1] = fmaxf(hnf[4 * k + 1], v.y);
                hnf[4 * k + 2] = fmaxf(hnf[4 * k + 2], v.z);
                hnf[4 * k + 3] = fmaxf(hnf[4 * k + 3], v.w);
            }
        }
#pragma unroll
        for (int j = 0; j < 32; j++) stag[(32 + j) * 256 + slot] = hnf[j];
    }

    // h2 = relu(af@Wself + hnf@Wneigh + bneigh), both nodes, full 64-wide accs
    {
        u64 acc0[32], acc1[32];
#pragma unroll
        for (int j = 0; j < 32; j++) { acc0[j] = sbn[j]; acc1[j] = sbn[j]; }
#pragma unroll
        for (int k = 0; k < 32; k++) {
            u64 av0 = pack2(stag[k * 256 + tid]);
            u64 av1 = pack2(stag[k * 256 + 128 + tid]);
            u64 bv0 = pack2(stag[(32 + k) * 256 + tid]);
            u64 bv1 = pack2(stag[(32 + k) * 256 + 128 + tid]);
            const ulonglong2* ps = (const ulonglong2*)&sWs[k * 32];
            const ulonglong2* pn = (const ulonglong2*)&sWn[k * 32];
#pragma unroll
            for (int jj = 0; jj < 16; jj++) {
                ulonglong2 w = ps[jj];
                fma2(acc0[2 * jj], av0, w.x);
                fma2(acc0[2 * jj + 1], av0, w.y);
                fma2(acc1[2 * jj], av1, w.x);
                fma2(acc1[2 * jj + 1], av1, w.y);
                ulonglong2 u = pn[jj];
                fma2(acc0[2 * jj], bv0, u.x);
                fma2(acc0[2 * jj + 1], bv0, u.y);
                fma2(acc1[2 * jj], bv1, u.x);
                fma2(acc1[2 * jj + 1], bv1, u.y);
            }
        }
        // relu(h2) overwrites staging channels 0..63
#pragma unroll
        for (int j = 0; j < 32; j++) {
            float2 f0 = unpack2(acc0[j]);
            float2 f1 = unpack2(acc1[j]);
            stag[(2 * j) * 256 + tid]           = fmaxf(f0.x, 0.f);
            stag[(2 * j + 1) * 256 + tid]       = fmaxf(f0.y, 0.f);
            stag[(2 * j) * 256 + 128 + tid]     = fmaxf(f1.x, 0.f);
            stag[(2 * j + 1) * 256 + 128 + tid] = fmaxf(f1.y, 0.f);
        }
    }

    // h3 = relu(h2@Wlin + blin), two 32-output halves; pooling folded per half
    int lane = tid & 31;
    int g00 = __shfl_sync(0xffffffffu, gid0, 0);
    bool uni0 = __all_sync(0xffffffffu, gid0 == g00);
    int g10 = __shfl_sync(0xffffffffu, gid1, 0);
    bool uni1 = __all_sync(0xffffffffu, gid1 == g10);

#pragma unroll
    for (int half = 0; half < 2; half++) {
        u64 a2_0[16], a2_1[16];
#pragma unroll
        for (int j = 0; j < 16; j++) { a2_0[j] = sbl[16 * half + j]; a2_1[j] = sbl[16 * half + j]; }
#pragma unroll
        for (int k2 = 0; k2 < 64; k2++) {
            u64 av0 = pack2(stag[k2 * 256 + tid]);
            u64 av1 = pack2(stag[k2 * 256 + 128 + tid]);
            const ulonglong2* pl = (const ulonglong2*)&sWl[k2 * 32 + 16 * half];
#pragma unroll
            for (int jj = 0; jj < 8; jj++) {
                ulonglong2 w = pl[jj];
                fma2(a2_0[2 * jj], av0, w.x);
                fma2(a2_0[2 * jj + 1], av0, w.y);
                fma2(a2_1[2 * jj], av1, w.x);
                fma2(a2_1[2 * jj + 1], av1, w.y);
            }
        }
#pragma unroll
        for (int n = 0; n < 2; n++) {
            bool valid = n ? valid1 : valid0;
            int gid = n ? gid1 : gid0;
            int g0 = n ? g10 : g00;
            bool uni = n ? uni1 : uni0;
            float v[32];
#pragma unroll
            for (int j = 0; j < 16; j++) {
                float2 f = unpack2(n ? a2_1[j] : a2_0[j]);
                v[2 * j]     = valid ? fmaxf(f.x, 0.f) : 0.f;
                v[2 * j + 1] = valid ? fmaxf(f.y, 0.f) : 0.f;
            }
            if (uni) {
                float o = 0.f;
#pragma unroll
                for (int j = 0; j < 32; j++) {
                    float x = v[j];
                    x += __shfl_xor_sync(0xffffffffu, x, 16);
                    x += __shfl_xor_sync(0xffffffffu, x, 8);
                    x += __shfl_xor_sync(0xffffffffu, x, 4);
                    x += __shfl_xor_sync(0xffffffffu, x, 2);
                    x += __shfl_xor_sync(0xffffffffu, x, 1);
                    if (lane == j) o = x;
                }
                atomicAdd(out + g0 * 64 + 32 * half + lane, o);
            } else if (valid) {
                float* row = out + gid * 64 + 32 * half;
#pragma unroll
                for (int j = 0; j < 32; j++) atomicAdd(row + j, v[j]);
            }
        }
    }
}

__global__ __launch_bounds__(128, 2) void k_out(
    const int* __restrict__ graph_ids,
    const float* __restrict__ Wself, const float* __restrict__ Wneigh,
    const float* __restrict__ bneigh,
    const float* __restrict__ Wlin, const float* __restrict__ blin,
    float* __restrict__ out)
{
    out_body(graph_ids, Wself, Wneigh, bneigh, Wlin, blin, out);
}

// profiling probe: identical body, scratch output, small grid.
__global__ __launch_bounds__(128, 2) void k_out_probe(
    const int* __restrict__ graph_ids,
    const float* __restrict__ Wself, const float* __restrict__ Wneigh,
    const float* __restrict__ bneigh,
    const float* __restrict__ Wlin, const float* __restrict__ blin)
{
    out_body(graph_ids, Wself, Wneigh, bneigh, Wlin, blin, g_probe_out);
}

// ---------------- launch ----------------
extern "C" void kernel_launch(void* const* d_in, const int* in_sizes, int n_in,
                              void* d_out, int out_size) {
    const int*   tokens    = (const int*)  d_in[0];
    const int*   edge_src  = (const int*)  d_in[1];
    const int*   edge_dst  = (const int*)  d_in[2];
    const int*   graph_ids = (const int*)  d_in[3];
    const float* embed     = (const float*)d_in[4];
    const float* W1        = (const float*)d_in[5];
    const float* b1        = (const float*)d_in[6];
    const float* Wpool     = (const float*)d_in[7];
    const float* bpool     = (const float*)d_in[8];
    const float* Wself     = (const float*)d_in[9];
    const float* Wneigh    = (const float*)d_in[10];
    const float* bneigh    = (const float*)d_in[11];
    const float* Wlin      = (const float*)d_in[12];
    const float* blin      = (const float*)d_in[13];
    float* out = (float*)d_out;

    const int STAG_BYTES = 64 * 256 * 4;   // 64KB dynamic staging
    cudaFuncSetAttribute(k_out,       cudaFuncAttributeMaxDynamicSharedMemorySize, STAG_BYTES);
    cudaFuncSetAttribute(k_out_probe, cudaFuncAttributeMaxDynamicSharedMemorySize, STAG_BYTES);

    const int TB = 256;
    int gridE = (NE + TB - 1) / TB;
    int gridN = (NN + TB - 1) / TB;
    int gridO = (NN + 255) / 256;   // 256 nodes per 128-thread block

    k_init<<<gridN, TB>>>(out);                                     // launch 1
    k_deg<<<gridE, TB>>>(edge_src, edge_dst);                       // launch 2
    k_scan_bsum <<<SCAN_NBLK, SCAN_BS>>>();                         // launch 3
    k_out_probe<<<148, 128, STAG_BYTES>>>(graph_ids, Wself, Wneigh, // launch 4 (ncu slot)
                                          bneigh, Wlin, blin);
    k_scan_top  <<<1, SCAN_BS>>>();                                 // launch 5
    k_scan_write<<<SCAN_NBLK, SCAN_BS>>>();                         // launch 6
    k_fill<<<gridE, TB>>>(edge_src, edge_dst);                      // launch 7
    k_h1<<<gridN, TB>>>(tokens, embed, W1, b1, Wpool, bpool);       // launch 8
    k_out<<<gridO, 128, STAG_BYTES>>>(graph_ids, Wself, Wneigh, bneigh, Wlin, blin, out);  // launch 9
}

// round 10
// speedup vs baseline: 1.4291x; 1.4291x over previous
#include <cuda_runtime.h>

#define NN 500000
#define NE 1000000
#define NG 512

#define SCAN_BS 256
#define SCAN_ELEMS 2048                       // 256 threads * 8
#define SCAN_NBLK ((NN + SCAN_ELEMS - 1) / SCAN_ELEMS)   // 245

#define STG 257                                // staging stride (bank-conflict pad)
#define STAG_BYTES (64 * STG * 4)

typedef unsigned long long u64;

// ---------------- scratch ----------------
__device__ int    g_cnt_out[NN];
__device__ int    g_cnt_in [NN];
__device__ float  g_ns     [NN];   // rsqrt(max(deg_out,1))
__device__ int    g_row_off[NN + 1];
__device__ int    g_cursor [NN];
__device__ int    g_csr_src[NE];
__device__ int    g_bsum [256];
__device__ int    g_bpref[256];
__device__ float4 g_h1[NN * 8];    // [N,32]
__device__ float4 g_hp[NN * 8];    // [N,32] relu(h1@Wpool+bpool)
__device__ float  g_probe_out[NG * 64];   // probe scratch (never read)

// ---------------- f32x2 helpers ----------------
__device__ __forceinline__ u64 pack2(float a) {
    u64 r;
    asm("mov.b64 %0, {%1, %1};" : "=l"(r) : "f"(a));
    return r;
}
__device__ __forceinline__ void fma2(u64& d, u64 a, u64 b) {
    asm("fma.rn.f32x2 %0, %1, %2, %0;" : "+l"(d) : "l"(a), "l"(b));
}
__device__ __forceinline__ float2 unpack2(u64 v) {
    float2 f;
    asm("mov.b64 {%0, %1}, %2;" : "=f"(f.x), "=f"(f.y) : "l"(v));
    return f;
}

// ---------------- init ----------------
__global__ void k_init(float* __restrict__ out) {
    int i = blockIdx.x * blockDim.x + threadIdx.x;
    if (i < NN) { g_cnt_out[i] = 0; g_cnt_in[i] = 0; }
    if (i < NG * 64) out[i] = 0.f;
}

// ---------------- degree counts ----------------
__global__ void k_deg(const int* __restrict__ src, const int* __restrict__ dst) {
    int e = blockIdx.x * blockDim.x + threadIdx.x;
    if (e < NE) {
        atomicAdd(&g_cnt_out[src[e]], 1);
        atomicAdd(&g_cnt_in [dst[e]], 1);
    }
}

// ---------------- scan pass 1 ----------------
__global__ __launch_bounds__(SCAN_BS) void k_scan_bsum() {
    __shared__ int sred[SCAN_BS];
    int b = blockIdx.x, t = threadIdx.x;
    int base = b * SCAN_ELEMS + t * 8;
    int s = 0;
#pragma unroll
    for (int k = 0; k < 8; k++) {
        int idx = base + k;
        if (idx < NN) s += g_cnt_in[idx];
    }
    sred[t] = s;
    __syncthreads();
    for (int o = SCAN_BS / 2; o > 0; o >>= 1) {
        if (t < o) sred[t] += sred[t + o];
        __syncthreads();
    }
    if (t == 0) g_bsum[b] = sred[0];
}

// ---------------- scan pass 2 ----------------
__global__ __launch_bounds__(SCAN_BS) void k_scan_top() {
    __shared__ int s[SCAN_BS];
    int t = threadIdx.x;
    int v = (t < SCAN_NBLK) ? g_bsum[t] : 0;
    s[t] = v;
    __syncthreads();
    for (int o = 1; o < SCAN_BS; o <<= 1) {
        int u = (t >= o) ? s[t - o] : 0;
        __syncthreads();
        s[t] += u;
        __syncthreads();
    }
    if (t < SCAN_NBLK) g_bpref[t] = s[t] - v;
    if (t == 0) g_row_off[NN] = NE;
}

// ---------------- scan pass 3 (also computes g_ns) ----------------
__global__ __launch_bounds__(SCAN_BS) void k_scan_write() {
    __shared__ int sth[SCAN_BS];
    int b = blockIdx.x, t = threadIdx.x;
    int base = b * SCAN_ELEMS + t * 8;
    int vals[8];
    int s = 0;
#pragma unroll
    for (int k = 0; k < 8; k++) {
        int idx = base + k;
        vals[k] = (idx < NN) ? g_cnt_in[idx] : 0;
        s += vals[k];
    }
    sth[t] = s;
    __syncthreads();
    int incl = s;
    for (int o = 1; o < SCAN_BS; o <<= 1) {
        int u = (t >= o) ? sth[t - o] : 0;
        __syncthreads();
        incl += u;
        sth[t] = incl;
        __syncthreads();
    }
    int run = g_bpref[b] + incl - s;
#pragma unroll
    for (int k = 0; k < 8; k++) {
        int idx = base + k;
        if (idx < NN) {
            g_row_off[idx] = run;
            g_cursor[idx] = run;
            g_ns[idx] = rsqrtf(fmaxf((float)g_cnt_out[idx], 1.0f));
        }
        run += vals[k];
    }
}

// ---------------- CSR fill ----------------
__global__ void k_fill(const int* __restrict__ src, const int* __restrict__ dst) {
    int e = blockIdx.x * blockDim.x + threadIdx.x;
    if (e < NE) {
        int p = atomicAdd(&g_cursor[dst[e]], 1);
        g_csr_src[p] = src[e];
    }
}

// ---------------- gather embed directly + MLP1 + pool MLP ----------------
__global__ __launch_bounds__(256) void k_h1(
    const int* __restrict__ tokens, const float* __restrict__ embed,
    const float* __restrict__ W1, const float* __restrict__ b1,
    const float* __restrict__ Wp, const float* __restrict__ bp)
{
    __shared__ __align__(16) u64 sW1[16 * 16], sWp[32 * 16];
    __shared__ u64 sb1[16], sbp[16];
    for (int t = threadIdx.x; t < 16 * 16; t += blockDim.x)
        ((float2*)sW1)[t] = ((const float2*)W1)[t];
    for (int t = threadIdx.x; t < 32 * 16; t += blockDim.x)
        ((float2*)sWp)[t] = ((const float2*)Wp)[t];
    for (int t = threadIdx.x; t < 16; t += blockDim.x) {
        ((float2*)sb1)[t] = ((const float2*)b1)[t];
        ((float2*)sbp)[t] = ((const float2*)bp)[t];
    }
    __syncthreads();

    int i = blockIdx.x * blockDim.x + threadIdx.x;
    if (i >= NN) return;

    int beg = g_row_off[i], end = g_row_off[i + 1];
    float4 a0 = make_float4(0, 0, 0, 0), a1 = a0, a2 = a0, a3 = a0;
    for (int e = beg; e < end; e++) {
        int s = g_csr_src[e];
        float ns = g_ns[s];
        const float4* er = (const float4*)(embed + (long)tokens[s] * 16);
        float4 v0 = er[0], v1 = er[1], v2 = er[2], v3 = er[3];
        a0.x += v0.x * ns; a0.y += v0.y * ns; a0.z += v0.z * ns; a0.w += v0.w * ns;
        a1.x += v1.x * ns; a1.y += v1.y * ns; a1.z += v1.z * ns; a1.w += v1.w * ns;
        a2.x += v2.x * ns; a2.y += v2.y * ns; a2.z += v2.z * ns; a2.w += v2.w * ns;
        a3.x += v3.x * ns; a3.y += v3.y * ns; a3.z += v3.z * ns; a3.w += v3.w * ns;
    }
    float nd = rsqrtf(fmaxf((float)(end - beg), 1.0f));
    float mr[16] = {a0.x * nd, a0.y * nd, a0.z * nd, a0.w * nd,
                    a1.x * nd, a1.y * nd, a1.z * nd, a1.w * nd,
                    a2.x * nd, a2.y * nd, a2.z * nd, a2.w * nd,
                    a3.x * nd, a3.y * nd, a3.z * nd, a3.w * nd};

    // h1 = relu(mr @ W1 + b1)
    u64 acc[16];
#pragma unroll
    for (int j = 0; j < 16; j++) acc[j] = sb1[j];
#pragma unroll
    for (int k = 0; k < 16; k++) {
        u64 av = pack2(mr[k]);
        const ulonglong2* pw = (const ulonglong2*)&sW1[k * 16];
#pragma unroll
        for (int jj = 0; jj < 8; jj++) {
            ulonglong2 w = pw[jj];
            fma2(acc[2 * jj], av, w.x);
            fma2(acc[2 * jj + 1], av, w.y);
        }
    }
    float h1f[32];
#pragma unroll
    for (int j = 0; j < 16; j++) {
        float2 f = unpack2(acc[j]);
        h1f[2 * j] = fmaxf(f.x, 0.f); h1f[2 * j + 1] = fmaxf(f.y, 0.f);
    }
#pragma unroll
    for (int k = 0; k < 8; k++)
        g_h1[i * 8 + k] = make_float4(h1f[4 * k], h1f[4 * k + 1], h1f[4 * k + 2], h1f[4 * k + 3]);

    // hp = relu(h1 @ Wpool + bpool)
    u64 pcc[16];
#pragma unroll
    for (int j = 0; j < 16; j++) pcc[j] = sbp[j];
#pragma unroll
    for (int k = 0; k < 32; k++) {
        u64 av = pack2(h1f[k]);
        const ulonglong2* pw = (const ulonglong2*)&sWp[k * 16];
#pragma unroll
        for (int jj = 0; jj < 8; jj++) {
            ulonglong2 w = pw[jj];
            fma2(pcc[2 * jj], av, w.x);
            fma2(pcc[2 * jj + 1], av, w.y);
        }
    }
#pragma unroll
    for (int j = 0; j < 8; j++) {
        float2 f0 = unpack2(pcc[2 * j]), f1 = unpack2(pcc[2 * j + 1]);
        g_hp[i * 8 + j] = make_float4(fmaxf(f0.x, 0.f), fmaxf(f0.y, 0.f),
                                      fmaxf(f1.x, 0.f), fmaxf(f1.y, 0.f));
    }
}

// ---------------- fused: gather-max + SAGE + lin + pooling ----------------
// Block = 256 nodes staged in smem (stride-257, conflict-free).
// Gather phase: 1 node/thread (full-width edge loop).
// Compute phases retiled: thread = 16 outputs (og=tid>>6) x 4 nodes
// {nt, nt+64, nt+128, nt+192} (nt=tid&63) -> each weight LDS.128 feeds 8 fma2,
// accumulators stay at 32 u64 (64 regs).
// Pooling: thread = channel (tid&63) x quarter (tid>>6), run-based sum over 64
// slots using per-slot graph ids in smem (graph_ids sorted -> ~1 run).
__device__ __forceinline__ void out_body(
    const int* __restrict__ graph_ids,
    const float* __restrict__ Wself, const float* __restrict__ Wneigh,
    const float* __restrict__ bneigh,
    const float* __restrict__ Wlin, const float* __restrict__ blin,
    float* __restrict__ out)
{
    __shared__ __align__(16) u64 sWs[32 * 32], sWn[32 * 32], sWl[64 * 32];
    __shared__ u64 sbn[32], sbl[32];
    __shared__ int sgid[256];
    extern __shared__ float stag[];   // 64 * STG floats

    for (int t = threadIdx.x; t < 32 * 32; t += blockDim.x) {
        ((float2*)sWs)[t] = ((const float2*)Wself)[t];
        ((float2*)sWn)[t] = ((const float2*)Wneigh)[t];
    }
    for (int t = threadIdx.x; t < 64 * 32; t += blockDim.x)
        ((float2*)sWl)[t] = ((const float2*)Wlin)[t];
    for (int t = threadIdx.x; t < 32; t += blockDim.x) {
        ((float2*)sbn)[t] = ((const float2*)bneigh)[t];
        ((float2*)sbl)[t] = ((const float2*)blin)[t];
    }

    int tid = threadIdx.x;
    int i = blockIdx.x * 256 + tid;
    bool valid = i < NN;
    int ic = valid ? i : NN - 1;
    sgid[tid] = valid ? graph_ids[ic] : -1;

    // ---- gather phase: 1 node/thread ----
#pragma unroll
    for (int k = 0; k < 8; k++) {
        float4 v = g_h1[(size_t)ic * 8 + k];
        stag[(4 * k + 0) * STG + tid] = v.x;
        stag[(4 * k + 1) * STG + tid] = v.y;
        stag[(4 * k + 2) * STG + tid] = v.z;
        stag[(4 * k + 3) * STG + tid] = v.w;
    }
    {
        float hnf[32];
#pragma unroll
        for (int j = 0; j < 32; j++) hnf[j] = 0.f;
        int beg = g_row_off[ic], end = g_row_off[ic + 1];
        for (int e = beg; e < end; e++) {
            const float4* hr = &g_hp[(size_t)g_csr_src[e] * 8];
#pragma unroll
            for (int k = 0; k < 8; k++) {
                float4 v = hr[k];
                hnf[4 * k + 0] = fmaxf(hnf[4 * k + 0], v.x);
                hnf[4 * k + 1] = fmaxf(hnf[4 * k + 1], v.y);
                hnf[4 * k + 2] = fmaxf(hnf[4 * k + 2], v.z);
                hnf[4 * k + 3] = fmaxf(hnf[4 * k + 3], v.w);
            }
        }
#pragma unroll
        for (int j = 0; j < 32; j++) stag[(32 + j) * STG + tid] = hnf[j];
    }
    __syncthreads();

    int og = tid >> 6;   // output group: 16 outputs (8 pairs) starting at og*16
    int nt = tid & 63;   // node set {nt, nt+64, nt+128, nt+192}

    // ---- h2 = relu(af@Wself + hnf@Wneigh + bneigh) ----
    u64 acc[4][8];
#pragma unroll
    for (int m = 0; m < 4; m++)
#pragma unroll
        for (int p = 0; p < 8; p++) acc[m][p] = sbn[og * 8 + p];
#pragma unroll
    for (int k = 0; k < 32; k++) {
        u64 a[4], b[4];
#pragma unroll
        for (int m = 0; m < 4; m++) {
            a[m] = pack2(stag[k * STG + nt + 64 * m]);
            b[m] = pack2(stag[(32 + k) * STG + nt + 64 * m]);
        }
        const ulonglong2* ps = (const ulonglong2*)&sWs[k * 32 + og * 8];
        const ulonglong2* pn = (const ulonglong2*)&sWn[k * 32 + og * 8];
#pragma unroll
        for (int jj = 0; jj < 4; jj++) {
            ulonglong2 w = ps[jj];
            ulonglong2 u = pn[jj];
#pragma unroll
            for (int m = 0; m < 4; m++) {
                fma2(acc[m][2 * jj], a[m], w.x);
                fma2(acc[m][2 * jj + 1], a[m], w.y);
                fma2(acc[m][2 * jj], b[m], u.x);
                fma2(acc[m][2 * jj + 1], b[m], u.y);
            }
        }
    }
    __syncthreads();   // all reads of channels 0..63 done before overwrite
#pragma unroll
    for (int m = 0; m < 4; m++)
#pragma unroll
        for (int p = 0; p < 8; p++) {
            float2 f = unpack2(acc[m][p]);
            stag[(og * 16 + 2 * p) * STG + nt + 64 * m]     = fmaxf(f.x, 0.f);
            stag[(og * 16 + 2 * p + 1) * STG + nt + 64 * m] = fmaxf(f.y, 0.f);
        }
    __syncthreads();

    // ---- h3 = relu(h2@Wlin + blin) ----
    u64 a2[4][8];
#pragma unroll
    for (int m = 0; m < 4; m++)
#pragma unroll
        for (int p = 0; p < 8; p++) a2[m][p] = sbl[og * 8 + p];
#pragma unroll
    for (int k2 = 0; k2 < 64; k2++) {
        u64 a[4];
#pragma unroll
        for (int m = 0; m < 4; m++) a[m] = pack2(stag[k2 * STG + nt + 64 * m]);
        const ulonglong2* pl = (const ulonglong2*)&sWl[k2 * 32 + og * 8];
#pragma unroll
        for (int jj = 0; jj < 4; jj++) {
            ulonglong2 w = pl[jj];
#pragma unroll
            for (int m = 0; m < 4; m++) {
                fma2(a2[m][2 * jj], a[m], w.x);
                fma2(a2[m][2 * jj + 1], a[m], w.y);
            }
        }
    }
    __syncthreads();
#pragma unroll
    for (int m = 0; m < 4; m++)
#pragma unroll
        for (int p = 0; p < 8; p++) {
            float2 f = unpack2(a2[m][p]);
            stag[(og * 16 + 2 * p) * STG + nt + 64 * m]     = fmaxf(f.x, 0.f);
            stag[(og * 16 + 2 * p + 1) * STG + nt + 64 * m] = fmaxf(f.y, 0.f);
        }
    __syncthreads();

    // ---- pooling: run-based sum over this quarter's 64 slots ----
    {
        int c = tid & 63;    // channel
        int q = tid >> 6;    // quarter
        float run = 0.f;
        int cur = -1;
        for (int s = 0; s < 64; s++) {
            int slot = q * 64 + s;
            int g = sgid[slot];
            float v = stag[c * STG + slot];
            if (g != cur) {
                if (cur >= 0) atomicAdd(out + cur * 64 + c, run);
                run = 0.f;
                cur = g;
            }
            if (g >= 0) run += v;
        }
        if (cur >= 0) atomicAdd(out + cur * 64 + c, run);
    }
}

__global__ __launch_bounds__(256, 2) void k_out(
    const int* __restrict__ graph_ids,
    const float* __restrict__ Wself, const float* __restrict__ Wneigh,
    const float* __restrict__ bneigh,
    const float* __restrict__ Wlin, const float* __restrict__ blin,
    float* __restrict__ out)
{
    out_body(graph_ids, Wself, Wneigh, bneigh, Wlin, blin, out);
}

// profiling probe: identical body, scratch output, 1 full wave (2 CTA/SM).
__global__ __launch_bounds__(256, 2) void k_out_probe(
    const int* __restrict__ graph_ids,
    const float* __restrict__ Wself, const float* __restrict__ Wneigh,
    const float* __restrict__ bneigh,
    const float* __restrict__ Wlin, const float* __restrict__ blin)
{
    out_body(graph_ids, Wself, Wneigh, bneigh, Wlin, blin, g_probe_out);
}

// ---------------- launch ----------------
extern "C" void kernel_launch(void* const* d_in, const int* in_sizes, int n_in,
                              void* d_out, int out_size) {
    const int*   tokens    = (const int*)  d_in[0];
    const int*   edge_src  = (const int*)  d_in[1];
    const int*   edge_dst  = (const int*)  d_in[2];
    const int*   graph_ids = (const int*)  d_in[3];
    const float* embed     = (const float*)d_in[4];
    const float* W1        = (const float*)d_in[5];
    const float* b1        = (const float*)d_in[6];
    const float* Wpool     = (const float*)d_in[7];
    const float* bpool     = (const float*)d_in[8];
    const float* Wself     = (const float*)d_in[9];
    const float* Wneigh    = (const float*)d_in[10];
    const float* bneigh    = (const float*)d_in[11];
    const float* Wlin      = (const float*)d_in[12];
    const float* blin      = (const float*)d_in[13];
    float* out = (float*)d_out;

    cudaFuncSetAttribute(k_out,       cudaFuncAttributeMaxDynamicSharedMemorySize, STAG_BYTES);
    cudaFuncSetAttribute(k_out_probe, cudaFuncAttributeMaxDynamicSharedMemorySize, STAG_BYTES);

    const int TB = 256;
    int gridE = (NE + TB - 1) / TB;
    int gridN = (NN + TB - 1) / TB;
    int gridO = (NN + 255) / 256;

    k_init<<<gridN, TB>>>(out);                                     // launch 1
    k_deg<<<gridE, TB>>>(edge_src, edge_dst);                       // launch 2
    k_scan_bsum <<<SCAN_NBLK, SCAN_BS>>>();                         // launch 3
    k_out_probe<<<296, TB, STAG_BYTES>>>(graph_ids, Wself, Wneigh,  // launch 4 (ncu slot)
                                         bneigh, Wlin, blin);
    k_scan_top  <<<1, SCAN_BS>>>();                                 // launch 5
    k_scan_write<<<SCAN_NBLK, SCAN_BS>>>();                         // launch 6
    k_fill<<<gridE, TB>>>(edge_src, edge_dst);                      // launch 7
    k_h1<<<gridN, TB>>>(tokens, embed, W1, b1, Wpool, bpool);       // launch 8
    k_out<<<gridO, TB, STAG_BYTES>>>(graph_ids, Wself, Wneigh, bneigh, Wlin, blin, out);  // launch 9
}

// round 11
// speedup vs baseline: 1.4982x; 1.0484x over previous
#include <cuda_runtime.h>

#define NN 500000
#define NE 1000000
#define NG 512

#define SCAN_BS 256
#define SCAN_ELEMS 2048                       // 256 threads * 8
#define SCAN_NBLK ((NN + SCAN_ELEMS - 1) / SCAN_ELEMS)   // 245

#define STG 257                                // staging stride (bank-conflict pad)
#define STAG_BYTES (64 * STG * 4)

typedef unsigned long long u64;

// ---------------- scratch ----------------
__device__ int    g_cnt_out[NN];
__device__ int    g_cnt_in [NN];
__device__ float  g_ns     [NN];   // rsqrt(max(deg_out,1))
__device__ int    g_row_off[NN + 1];
__device__ int    g_cursor [NN];
__device__ int    g_csr_src[NE];
__device__ int    g_bsum [256];
__device__ int    g_bpref[256];
__device__ float4 g_h1[NN * 8];    // [N,32]
__device__ float4 g_hp[NN * 8];    // [N,32] relu(h1@Wpool+bpool)

// ---------------- f32x2 helpers ----------------
__device__ __forceinline__ u64 pack2(float a) {
    u64 r;
    asm("mov.b64 %0, {%1, %1};" : "=l"(r) : "f"(a));
    return r;
}
__device__ __forceinline__ void fma2(u64& d, u64 a, u64 b) {
    asm("fma.rn.f32x2 %0, %1, %2, %0;" : "+l"(d) : "l"(a), "l"(b));
}
__device__ __forceinline__ float2 unpack2(u64 v) {
    float2 f;
    asm("mov.b64 {%0, %1}, %2;" : "=f"(f.x), "=f"(f.y) : "l"(v));
    return f;
}

// ---------------- init ----------------
__global__ void k_init(float* __restrict__ out) {
    int i = blockIdx.x * blockDim.x + threadIdx.x;
    if (i < NN) { g_cnt_out[i] = 0; g_cnt_in[i] = 0; }
    if (i < NG * 64) out[i] = 0.f;
}

// ---------------- degree counts ----------------
__global__ void k_deg(const int* __restrict__ src, const int* __restrict__ dst) {
    int e = blockIdx.x * blockDim.x + threadIdx.x;
    if (e < NE) {
        atomicAdd(&g_cnt_out[src[e]], 1);
        atomicAdd(&g_cnt_in [dst[e]], 1);
    }
}

// ---------------- scan pass 1 ----------------
__global__ __launch_bounds__(SCAN_BS) void k_scan_bsum() {
    __shared__ int sred[SCAN_BS];
    int b = blockIdx.x, t = threadIdx.x;
    int base = b * SCAN_ELEMS + t * 8;
    int s = 0;
#pragma unroll
    for (int k = 0; k < 8; k++) {
        int idx = base + k;
        if (idx < NN) s += g_cnt_in[idx];
    }
    sred[t] = s;
    __syncthreads();
    for (int o = SCAN_BS / 2; o > 0; o >>= 1) {
        if (t < o) sred[t] += sred[t + o];
        __syncthreads();
    }
    if (t == 0) g_bsum[b] = sred[0];
}

// ---------------- scan pass 2 ----------------
__global__ __launch_bounds__(SCAN_BS) void k_scan_top() {
    __shared__ int s[SCAN_BS];
    int t = threadIdx.x;
    int v = (t < SCAN_NBLK) ? g_bsum[t] : 0;
    s[t] = v;
    __syncthreads();
    for (int o = 1; o < SCAN_BS; o <<= 1) {
        int u = (t >= o) ? s[t - o] : 0;
        __syncthreads();
        s[t] += u;
        __syncthreads();
    }
    if (t < SCAN_NBLK) g_bpref[t] = s[t] - v;
    if (t == 0) g_row_off[NN] = NE;
}

// ---------------- scan pass 3 (also computes g_ns) ----------------
__global__ __launch_bounds__(SCAN_BS) void k_scan_write() {
    __shared__ int sth[SCAN_BS];
    int b = blockIdx.x, t = threadIdx.x;
    int base = b * SCAN_ELEMS + t * 8;
    int vals[8];
    int s = 0;
#pragma unroll
    for (int k = 0; k < 8; k++) {
        int idx = base + k;
        vals[k] = (idx < NN) ? g_cnt_in[idx] : 0;
        s += vals[k];
    }
    sth[t] = s;
    __syncthreads();
    int incl = s;
    for (int o = 1; o < SCAN_BS; o <<= 1) {
        int u = (t >= o) ? sth[t - o] : 0;
        __syncthreads();
        incl += u;
        sth[t] = incl;
        __syncthreads();
    }
    int run = g_bpref[b] + incl - s;
#pragma unroll
    for (int k = 0; k < 8; k++) {
        int idx = base + k;
        if (idx < NN) {
            g_row_off[idx] = run;
            g_cursor[idx] = run;
            g_ns[idx] = rsqrtf(fmaxf((float)g_cnt_out[idx], 1.0f));
        }
        run += vals[k];
    }
}

// ---------------- CSR fill ----------------
__global__ void k_fill(const int* __restrict__ src, const int* __restrict__ dst) {
    int e = blockIdx.x * blockDim.x + threadIdx.x;
    if (e < NE) {
        int p = atomicAdd(&g_cursor[dst[e]], 1);
        g_csr_src[p] = src[e];
    }
}

// ---------------- gather embed directly + MLP1 + pool MLP ----------------
// BODY shared between the real kernel and the profiling probe.
__device__ __forceinline__ void h1_body(
    const int* __restrict__ tokens, const float* __restrict__ embed,
    const float* __restrict__ W1, const float* __restrict__ b1,
    const float* __restrict__ Wp, const float* __restrict__ bp)
{
    __shared__ __align__(16) u64 sW1[16 * 16], sWp[32 * 16];
    __shared__ u64 sb1[16], sbp[16];
    for (int t = threadIdx.x; t < 16 * 16; t += blockDim.x)
        ((float2*)sW1)[t] = ((const float2*)W1)[t];
    for (int t = threadIdx.x; t < 32 * 16; t += blockDim.x)
        ((float2*)sWp)[t] = ((const float2*)Wp)[t];
    for (int t = threadIdx.x; t < 16; t += blockDim.x) {
        ((float2*)sb1)[t] = ((const float2*)b1)[t];
        ((float2*)sbp)[t] = ((const float2*)bp)[t];
    }
    __syncthreads();

    int i = blockIdx.x * blockDim.x + threadIdx.x;
    if (i >= NN) return;

    int beg = g_row_off[i], end = g_row_off[i + 1];
    float4 a0 = make_float4(0, 0, 0, 0), a1 = a0, a2 = a0, a3 = a0;
    for (int e = beg; e < end; e++) {
        int s = g_csr_src[e];
        float ns = g_ns[s];
        const float4* er = (const float4*)(embed + (long)tokens[s] * 16);
        float4 v0 = er[0], v1 = er[1], v2 = er[2], v3 = er[3];
        a0.x += v0.x * ns; a0.y += v0.y * ns; a0.z += v0.z * ns; a0.w += v0.w * ns;
        a1.x += v1.x * ns; a1.y += v1.y * ns; a1.z += v1.z * ns; a1.w += v1.w * ns;
        a2.x += v2.x * ns; a2.y += v2.y * ns; a2.z += v2.z * ns; a2.w += v2.w * ns;
        a3.x += v3.x * ns; a3.y += v3.y * ns; a3.z += v3.z * ns; a3.w += v3.w * ns;
    }
    float nd = rsqrtf(fmaxf((float)(end - beg), 1.0f));
    float mr[16] = {a0.x * nd, a0.y * nd, a0.z * nd, a0.w * nd,
                    a1.x * nd, a1.y * nd, a1.z * nd, a1.w * nd,
                    a2.x * nd, a2.y * nd, a2.z * nd, a2.w * nd,
                    a3.x * nd, a3.y * nd, a3.z * nd, a3.w * nd};

    // h1 = relu(mr @ W1 + b1)
    u64 acc[16];
#pragma unroll
    for (int j = 0; j < 16; j++) acc[j] = sb1[j];
#pragma unroll
    for (int k = 0; k < 16; k++) {
        u64 av = pack2(mr[k]);
        const ulonglong2* pw = (const ulonglong2*)&sW1[k * 16];
#pragma unroll
        for (int jj = 0; jj < 8; jj++) {
            ulonglong2 w = pw[jj];
            fma2(acc[2 * jj], av, w.x);
            fma2(acc[2 * jj + 1], av, w.y);
        }
    }
    float h1f[32];
#pragma unroll
    for (int j = 0; j < 16; j++) {
        float2 f = unpack2(acc[j]);
        h1f[2 * j] = fmaxf(f.x, 0.f); h1f[2 * j + 1] = fmaxf(f.y, 0.f);
    }
#pragma unroll
    for (int k = 0; k < 8; k++)
        g_h1[i * 8 + k] = make_float4(h1f[4 * k], h1f[4 * k + 1], h1f[4 * k + 2], h1f[4 * k + 3]);

    // hp = relu(h1 @ Wpool + bpool)
    u64 pcc[16];
#pragma unroll
    for (int j = 0; j < 16; j++) pcc[j] = sbp[j];
#pragma unroll
    for (int k = 0; k < 32; k++) {
        u64 av = pack2(h1f[k]);
        const ulonglong2* pw = (const ulonglong2*)&sWp[k * 16];
#pragma unroll
        for (int jj = 0; jj < 8; jj++) {
            ulonglong2 w = pw[jj];
            fma2(pcc[2 * jj], av, w.x);
            fma2(pcc[2 * jj + 1], av, w.y);
        }
    }
#pragma unroll
    for (int j = 0; j < 8; j++) {
        float2 f0 = unpack2(pcc[2 * j]), f1 = unpack2(pcc[2 * j + 1]);
        g_hp[i * 8 + j] = make_float4(fmaxf(f0.x, 0.f), fmaxf(f0.y, 0.f),
                                      fmaxf(f1.x, 0.f), fmaxf(f1.y, 0.f));
    }
}

__global__ __launch_bounds__(256) void k_h1(
    const int* __restrict__ tokens, const float* __restrict__ embed,
    const float* __restrict__ W1, const float* __restrict__ b1,
    const float* __restrict__ Wp, const float* __restrict__ bp)
{
    h1_body(tokens, embed, W1, b1, Wp, bp);
}

// profiling probe: identical body, small grid. Reads stale CSR/g_ns
// (deterministic across replays); writes g_h1/g_hp regions that the real
// k_h1 (launched later) fully overwrites.
__global__ __launch_bounds__(256) void k_h1_probe(
    const int* __restrict__ tokens, const float* __restrict__ embed,
    const float* __restrict__ W1, const float* __restrict__ b1,
    const float* __restrict__ Wp, const float* __restrict__ bp)
{
    h1_body(tokens, embed, W1, b1, Wp, bp);
}

// ---------------- fused: gather-max + SAGE + lin + pooling ----------------
// Block = 256 nodes staged in smem (stride-257, conflict-free).
// Gather phase: 1 node/thread. Compute phases: thread = 16 outputs x 4 nodes.
// Pooling: thread = channel x quarter, run-based sum with per-slot graph ids.
__global__ __launch_bounds__(256, 2) void k_out(
    const int* __restrict__ graph_ids,
    const float* __restrict__ Wself, const float* __restrict__ Wneigh,
    const float* __restrict__ bneigh,
    const float* __restrict__ Wlin, const float* __restrict__ blin,
    float* __restrict__ out)
{
    __shared__ __align__(16) u64 sWs[32 * 32], sWn[32 * 32], sWl[64 * 32];
    __shared__ u64 sbn[32], sbl[32];
    __shared__ int sgid[256];
    extern __shared__ float stag[];   // 64 * STG floats

    for (int t = threadIdx.x; t < 32 * 32; t += blockDim.x) {
        ((float2*)sWs)[t] = ((const float2*)Wself)[t];
        ((float2*)sWn)[t] = ((const float2*)Wneigh)[t];
    }
    for (int t = threadIdx.x; t < 64 * 32; t += blockDim.x)
        ((float2*)sWl)[t] = ((const float2*)Wlin)[t];
    for (int t = threadIdx.x; t < 32; t += blockDim.x) {
        ((float2*)sbn)[t] = ((const float2*)bneigh)[t];
        ((float2*)sbl)[t] = ((const float2*)blin)[t];
    }

    int tid = threadIdx.x;
    int i = blockIdx.x * 256 + tid;
    bool valid = i < NN;
    int ic = valid ? i : NN - 1;
    sgid[tid] = valid ? graph_ids[ic] : -1;

    // ---- gather phase: 1 node/thread ----
#pragma unroll
    for (int k = 0; k < 8; k++) {
        float4 v = g_h1[(size_t)ic * 8 + k];
        stag[(4 * k + 0) * STG + tid] = v.x;
        stag[(4 * k + 1) * STG + tid] = v.y;
        stag[(4 * k + 2) * STG + tid] = v.z;
        stag[(4 * k + 3) * STG + tid] = v.w;
    }
    {
        float hnf[32];
#pragma unroll
        for (int j = 0; j < 32; j++) hnf[j] = 0.f;
        int beg = g_row_off[ic], end = g_row_off[ic + 1];
        for (int e = beg; e < end; e++) {
            const float4* hr = &g_hp[(size_t)g_csr_src[e] * 8];
#pragma unroll
            for (int k = 0; k < 8; k++) {
                float4 v = hr[k];
                hnf[4 * k + 0] = fmaxf(hnf[4 * k + 0], v.x);
                hnf[4 * k + 1] = fmaxf(hnf[4 * k + 1], v.y);
                hnf[4 * k + 2] = fmaxf(hnf[4 * k + 2], v.z);
                hnf[4 * k + 3] = fmaxf(hnf[4 * k + 3], v.w);
            }
        }
#pragma unroll
        for (int j = 0; j < 32; j++) stag[(32 + j) * STG + tid] = hnf[j];
    }
    __syncthreads();

    int og = tid >> 6;   // output group: 16 outputs (8 pairs) starting at og*16
    int nt = tid & 63;   // node set {nt, nt+64, nt+128, nt+192}

    // ---- h2 = relu(af@Wself + hnf@Wneigh + bneigh) ----
    u64 acc[4][8];
#pragma unroll
    for (int m = 0; m < 4; m++)
#pragma unroll
        for (int p = 0; p < 8; p++) acc[m][p] = sbn[og * 8 + p];
#pragma unroll
    for (int k = 0; k < 32; k++) {
        u64 a[4], b[4];
#pragma unroll
        for (int m = 0; m < 4; m++) {
            a[m] = pack2(stag[k * STG + nt + 64 * m]);
            b[m] = pack2(stag[(32 + k) * STG + nt + 64 * m]);
        }
        const ulonglong2* ps = (const ulonglong2*)&sWs[k * 32 + og * 8];
        const ulonglong2* pn = (const ulonglong2*)&sWn[k * 32 + og * 8];
#pragma unroll
        for (int jj = 0; jj < 4; jj++) {
            ulonglong2 w = ps[jj];
            ulonglong2 u = pn[jj];
#pragma unroll
            for (int m = 0; m < 4; m++) {
                fma2(acc[m][2 * jj], a[m], w.x);
                fma2(acc[m][2 * jj + 1], a[m], w.y);
                fma2(acc[m][2 * jj], b[m], u.x);
                fma2(acc[m][2 * jj + 1], b[m], u.y);
            }
        }
    }
    __syncthreads();   // all reads of channels 0..63 done before overwrite
#pragma unroll
    for (int m = 0; m < 4; m++)
#pragma unroll
        for (int p = 0; p < 8; p++) {
            float2 f = unpack2(acc[m][p]);
            stag[(og * 16 + 2 * p) * STG + nt + 64 * m]     = fmaxf(f.x, 0.f);
            stag[(og * 16 + 2 * p + 1) * STG + nt + 64 * m] = fmaxf(f.y, 0.f);
        }
    __syncthreads();

    // ---- h3 = relu(h2@Wlin + blin) ----
    u64 a2[4][8];
#pragma unroll
    for (int m = 0; m < 4; m++)
#pragma unroll
        for (int p = 0; p < 8; p++) a2[m][p] = sbl[og * 8 + p];
#pragma unroll
    for (int k2 = 0; k2 < 64; k2++) {
        u64 a[4];
#pragma unroll
        for (int m = 0; m < 4; m++) a[m] = pack2(stag[k2 * STG + nt + 64 * m]);
        const ulonglong2* pl = (const ulonglong2*)&sWl[k2 * 32 + og * 8];
#pragma unroll
        for (int jj = 0; jj < 4; jj++) {
            ulonglong2 w = pl[jj];
#pragma unroll
            for (int m = 0; m < 4; m++) {
                fma2(a2[m][2 * jj], a[m], w.x);
                fma2(a2[m][2 * jj + 1], a[m], w.y);
            }
        }
    }
    __syncthreads();
#pragma unroll
    for (int m = 0; m < 4; m++)
#pragma unroll
        for (int p = 0; p < 8; p++) {
            float2 f = unpack2(a2[m][p]);
            stag[(og * 16 + 2 * p) * STG + nt + 64 * m]     = fmaxf(f.x, 0.f);
            stag[(og * 16 + 2 * p + 1) * STG + nt + 64 * m] = fmaxf(f.y, 0.f);
        }
    __syncthreads();

    // ---- pooling: run-based sum over this quarter's 64 slots ----
    {
        int c = tid & 63;    // channel
        int q = tid >> 6;    // quarter
        float run = 0.f;
        int cur = -1;
        for (int s = 0; s < 64; s++) {
            int slot = q * 64 + s;
            int g = sgid[slot];
            float v = stag[c * STG + slot];
            if (g != cur) {
                if (cur >= 0) atomicAdd(out + cur * 64 + c, run);
                run = 0.f;
                cur = g;
            }
            if (g >= 0) run += v;
        }
        if (cur >= 0) atomicAdd(out + cur * 64 + c, run);
    }
}

// ---------------- launch ----------------
extern "C" void kernel_launch(void* const* d_in, const int* in_sizes, int n_in,
                              void* d_out, int out_size) {
    const int*   tokens    = (const int*)  d_in[0];
    const int*   edge_src  = (const int*)  d_in[1];
    const int*   edge_dst  = (const int*)  d_in[2];
    const int*   graph_ids = (const int*)  d_in[3];
    const float* embed     = (const float*)d_in[4];
    const float* W1        = (const float*)d_in[5];
    const float* b1        = (const float*)d_in[6];
    const float* Wpool     = (const float*)d_in[7];
    const float* bpool     = (const float*)d_in[8];
    const float* Wself     = (const float*)d_in[9];
    const float* Wneigh    = (const float*)d_in[10];
    const float* bneigh    = (const float*)d_in[11];
    const float* Wlin      = (const float*)d_in[12];
    const float* blin      = (const float*)d_in[13];
    float* out = (float*)d_out;

    cudaFuncSetAttribute(k_out, cudaFuncAttributeMaxDynamicSharedMemorySize, STAG_BYTES);

    const int TB = 256;
    int gridE = (NE + TB - 1) / TB;
    int gridN = (NN + TB - 1) / TB;
    int gridO = (NN + 255) / 256;

    k_init<<<gridN, TB>>>(out);                                     // launch 1
    k_deg<<<gridE, TB>>>(edge_src, edge_dst);                       // launch 2
    k_scan_bsum <<<SCAN_NBLK, SCAN_BS>>>();                         // launch 3
    k_h1_probe<<<296, TB>>>(tokens, embed, W1, b1, Wpool, bpool);   // launch 4 (ncu slot)
    k_scan_top  <<<1, SCAN_BS>>>();                                 // launch 5
    k_scan_write<<<SCAN_NBLK, SCAN_BS>>>();                         // launch 6
    k_fill<<<gridE, TB>>>(edge_src, edge_dst);                      // launch 7
    k_h1<<<gridN, TB>>>(tokens, embed, W1, b1, Wpool, bpool);       // launch 8
    k_out<<<gridO, TB, STAG_BYTES>>>(graph_ids, Wself, Wneigh, bneigh, Wlin, blin, out);  // launch 9
}

// round 12
// speedup vs baseline: 1.5300x; 1.0212x over previous
#include <cuda_runtime.h>

#define NN 500000
#define NE 1000000
#define NG 512

#define SCAN_BS 256
#define SCAN_ELEMS 2048                       // 256 threads * 8
#define SCAN_NBLK ((NN + SCAN_ELEMS - 1) / SCAN_ELEMS)   // 245

#define STG 257                                // staging stride (bank-conflict pad)
#define STAG_BYTES (64 * STG * 4)

typedef unsigned long long u64;

// ---------------- scratch ----------------
__device__ int    g_cnt_out[NN];
__device__ int    g_cnt_in [NN];
__device__ float  g_ns     [NN];   // rsqrt(max(deg_out,1))
__device__ int    g_row_off[NN + 1];
__device__ int    g_cursor [NN];
__device__ int    g_csr_src[NE];   // for k_out gather-max
__device__ int    g_csr_tok[NE];   // token of src  (k_h1 gather, de-hopped)
__device__ float  g_csr_ns [NE];   // ns of src     (k_h1 gather, de-hopped)
__device__ int    g_bsum [256];
__device__ int    g_bpref[256];
__device__ float4 g_h1[NN * 8];    // [N,32]
__device__ float4 g_hp[NN * 8];    // [N,32] relu(h1@Wpool+bpool)

// ---------------- f32x2 helpers ----------------
__device__ __forceinline__ u64 pack2(float a) {
    u64 r;
    asm("mov.b64 %0, {%1, %1};" : "=l"(r) : "f"(a));
    return r;
}
__device__ __forceinline__ void fma2(u64& d, u64 a, u64 b) {
    asm("fma.rn.f32x2 %0, %1, %2, %0;" : "+l"(d) : "l"(a), "l"(b));
}
__device__ __forceinline__ float2 unpack2(u64 v) {
    float2 f;
    asm("mov.b64 {%0, %1}, %2;" : "=f"(f.x), "=f"(f.y) : "l"(v));
    return f;
}

// ---------------- init ----------------
__global__ void k_init(float* __restrict__ out) {
    int i = blockIdx.x * blockDim.x + threadIdx.x;
    if (i < NN) { g_cnt_out[i] = 0; g_cnt_in[i] = 0; }
    if (i < NG * 64) out[i] = 0.f;
}

// ---------------- degree counts ----------------
__global__ void k_deg(const int* __restrict__ src, const int* __restrict__ dst) {
    int e = blockIdx.x * blockDim.x + threadIdx.x;
    if (e < NE) {
        atomicAdd(&g_cnt_out[src[e]], 1);
        atomicAdd(&g_cnt_in [dst[e]], 1);
    }
}

// ---------------- scan pass 1 ----------------
__global__ __launch_bounds__(SCAN_BS) void k_scan_bsum() {
    __shared__ int sred[SCAN_BS];
    int b = blockIdx.x, t = threadIdx.x;
    int base = b * SCAN_ELEMS + t * 8;
    int s = 0;
#pragma unroll
    for (int k = 0; k < 8; k++) {
        int idx = base + k;
        if (idx < NN) s += g_cnt_in[idx];
    }
    sred[t] = s;
    __syncthreads();
    for (int o = SCAN_BS / 2; o > 0; o >>= 1) {
        if (t < o) sred[t] += sred[t + o];
        __syncthreads();
    }
    if (t == 0) g_bsum[b] = sred[0];
}

// ---------------- scan pass 2 ----------------
__global__ __launch_bounds__(SCAN_BS) void k_scan_top() {
    __shared__ int s[SCAN_BS];
    int t = threadIdx.x;
    int v = (t < SCAN_NBLK) ? g_bsum[t] : 0;
    s[t] = v;
    __syncthreads();
    for (int o = 1; o < SCAN_BS; o <<= 1) {
        int u = (t >= o) ? s[t - o] : 0;
        __syncthreads();
        s[t] += u;
        __syncthreads();
    }
    if (t < SCAN_NBLK) g_bpref[t] = s[t] - v;
    if (t == 0) g_row_off[NN] = NE;
}

// ---------------- scan pass 3 (also computes g_ns) ----------------
__global__ __launch_bounds__(SCAN_BS) void k_scan_write() {
    __shared__ int sth[SCAN_BS];
    int b = blockIdx.x, t = threadIdx.x;
    int base = b * SCAN_ELEMS + t * 8;
    int vals[8];
    int s = 0;
#pragma unroll
    for (int k = 0; k < 8; k++) {
        int idx = base + k;
        vals[k] = (idx < NN) ? g_cnt_in[idx] : 0;
        s += vals[k];
    }
    sth[t] = s;
    __syncthreads();
    int incl = s;
    for (int o = 1; o < SCAN_BS; o <<= 1) {
        int u = (t >= o) ? sth[t - o] : 0;
        __syncthreads();
        incl += u;
        sth[t] = incl;
        __syncthreads();
    }
    int run = g_bpref[b] + incl - s;
#pragma unroll
    for (int k = 0; k < 8; k++) {
        int idx = base + k;
        if (idx < NN) {
            g_row_off[idx] = run;
            g_cursor[idx] = run;
            g_ns[idx] = rsqrtf(fmaxf((float)g_cnt_out[idx], 1.0f));
        }
        run += vals[k];
    }
}

// ---------------- CSR fill (also de-hops k_h1's gather) ----------------
// Runs after scan_write, so g_ns is ready. Massively edge-parallel: the
// dependent loads tokens[s] / g_ns[s] are latency-hidden here, removing
// two hops from k_h1's per-edge chain.
__global__ void k_fill(const int* __restrict__ src, const int* __restrict__ dst,
                       const int* __restrict__ tokens) {
    int e = blockIdx.x * blockDim.x + threadIdx.x;
    if (e < NE) {
        int s = src[e];
        int p = atomicAdd(&g_cursor[dst[e]], 1);
        g_csr_src[p] = s;
        g_csr_tok[p] = tokens[s];
        g_csr_ns [p] = g_ns[s];
    }
}

// ---------------- gather embed (1-hop) + MLP1 + pool MLP ----------------
__global__ __launch_bounds__(256) void k_h1(
    const float* __restrict__ embed,
    const float* __restrict__ W1, const float* __restrict__ b1,
    const float* __restrict__ Wp, const float* __restrict__ bp)
{
    __shared__ __align__(16) u64 sW1[16 * 16], sWp[32 * 16];
    __shared__ u64 sb1[16], sbp[16];
    for (int t = threadIdx.x; t < 16 * 16; t += blockDim.x)
        ((float2*)sW1)[t] = ((const float2*)W1)[t];
    for (int t = threadIdx.x; t < 32 * 16; t += blockDim.x)
        ((float2*)sWp)[t] = ((const float2*)Wp)[t];
    for (int t = threadIdx.x; t < 16; t += blockDim.x) {
        ((float2*)sb1)[t] = ((const float2*)b1)[t];
        ((float2*)sbp)[t] = ((const float2*)bp)[t];
    }
    __syncthreads();

    int i = blockIdx.x * blockDim.x + threadIdx.x;
    if (i >= NN) return;

    int beg = g_row_off[i], end = g_row_off[i + 1];
    float4 a0 = make_float4(0, 0, 0, 0), a1 = a0, a2 = a0, a3 = a0;
    for (int e = beg; e < end; e++) {
        int tok = g_csr_tok[e];            // streaming
        float ns = g_csr_ns[e];            // streaming
        const float4* er = (const float4*)(embed + (long)tok * 16);  // 1 dependent hop
        float4 v0 = er[0], v1 = er[1], v2 = er[2], v3 = er[3];
        a0.x += v0.x * ns; a0.y += v0.y * ns; a0.z += v0.z * ns; a0.w += v0.w * ns;
        a1.x += v1.x * ns; a1.y += v1.y * ns; a1.z += v1.z * ns; a1.w += v1.w * ns;
        a2.x += v2.x * ns; a2.y += v2.y * ns; a2.z += v2.z * ns; a2.w += v2.w * ns;
        a3.x += v3.x * ns; a3.y += v3.y * ns; a3.z += v3.z * ns; a3.w += v3.w * ns;
    }
    float nd = rsqrtf(fmaxf((float)(end - beg), 1.0f));
    float mr[16] = {a0.x * nd, a0.y * nd, a0.z * nd, a0.w * nd,
                    a1.x * nd, a1.y * nd, a1.z * nd, a1.w * nd,
                    a2.x * nd, a2.y * nd, a2.z * nd, a2.w * nd,
                    a3.x * nd, a3.y * nd, a3.z * nd, a3.w * nd};

    // h1 = relu(mr @ W1 + b1)
    u64 acc[16];
#pragma unroll
    for (int j = 0; j < 16; j++) acc[j] = sb1[j];
#pragma unroll
    for (int k = 0; k < 16; k++) {
        u64 av = pack2(mr[k]);
        const ulonglong2* pw = (const ulonglong2*)&sW1[k * 16];
#pragma unroll
        for (int jj = 0; jj < 8; jj++) {
            ulonglong2 w = pw[jj];
            fma2(acc[2 * jj], av, w.x);
            fma2(acc[2 * jj + 1], av, w.y);
        }
    }
    float h1f[32];
#pragma unroll
    for (int j = 0; j < 16; j++) {
        float2 f = unpack2(acc[j]);
        h1f[2 * j] = fmaxf(f.x, 0.f); h1f[2 * j + 1] = fmaxf(f.y, 0.f);
    }
#pragma unroll
    for (int k = 0; k < 8; k++)
        g_h1[i * 8 + k] = make_float4(h1f[4 * k], h1f[4 * k + 1], h1f[4 * k + 2], h1f[4 * k + 3]);

    // hp = relu(h1 @ Wpool + bpool)
    u64 pcc[16];
#pragma unroll
    for (int j = 0; j < 16; j++) pcc[j] = sbp[j];
#pragma unroll
    for (int k = 0; k < 32; k++) {
        u64 av = pack2(h1f[k]);
        const ulonglong2* pw = (const ulonglong2*)&sWp[k * 16];
#pragma unroll
        for (int jj = 0; jj < 8; jj++) {
            ulonglong2 w = pw[jj];
            fma2(pcc[2 * jj], av, w.x);
            fma2(pcc[2 * jj + 1], av, w.y);
        }
    }
#pragma unroll
    for (int j = 0; j < 8; j++) {
        float2 f0 = unpack2(pcc[2 * j]), f1 = unpack2(pcc[2 * j + 1]);
        g_hp[i * 8 + j] = make_float4(fmaxf(f0.x, 0.f), fmaxf(f0.y, 0.f),
                                      fmaxf(f1.x, 0.f), fmaxf(f1.y, 0.f));
    }
}

// ---------------- fused: gather-max + SAGE + lin + pooling ----------------
// Block = 256 nodes staged in smem (stride-257, conflict-free).
// Gather phase: 1 node/thread. Compute phases: thread = 16 outputs x 4 nodes.
// Pooling: thread = channel x quarter, run-based sum with per-slot graph ids.
__global__ __launch_bounds__(256, 2) void k_out(
    const int* __restrict__ graph_ids,
    const float* __restrict__ Wself, const float* __restrict__ Wneigh,
    const float* __restrict__ bneigh,
    const float* __restrict__ Wlin, const float* __restrict__ blin,
    float* __restrict__ out)
{
    __shared__ __align__(16) u64 sWs[32 * 32], sWn[32 * 32], sWl[64 * 32];
    __shared__ u64 sbn[32], sbl[32];
    __shared__ int sgid[256];
    extern __shared__ float stag[];   // 64 * STG floats

    for (int t = threadIdx.x; t < 32 * 32; t += blockDim.x) {
        ((float2*)sWs)[t] = ((const float2*)Wself)[t];
        ((float2*)sWn)[t] = ((const float2*)Wneigh)[t];
    }
    for (int t = threadIdx.x; t < 64 * 32; t += blockDim.x)
        ((float2*)sWl)[t] = ((const float2*)Wlin)[t];
    for (int t = threadIdx.x; t < 32; t += blockDim.x) {
        ((float2*)sbn)[t] = ((const float2*)bneigh)[t];
        ((float2*)sbl)[t] = ((const float2*)blin)[t];
    }

    int tid = threadIdx.x;
    int i = blockIdx.x * 256 + tid;
    bool valid = i < NN;
    int ic = valid ? i : NN - 1;
    sgid[tid] = valid ? graph_ids[ic] : -1;

    // ---- gather phase: 1 node/thread ----
#pragma unroll
    for (int k = 0; k < 8; k++) {
        float4 v = g_h1[(size_t)ic * 8 + k];
        stag[(4 * k + 0) * STG + tid] = v.x;
        stag[(4 * k + 1) * STG + tid] = v.y;
        stag[(4 * k + 2) * STG + tid] = v.z;
        stag[(4 * k + 3) * STG + tid] = v.w;
    }
    {
        float hnf[32];
#pragma unroll
        for (int j = 0; j < 32; j++) hnf[j] = 0.f;
        int beg = g_row_off[ic], end = g_row_off[ic + 1];
        for (int e = beg; e < end; e++) {
            const float4* hr = &g_hp[(size_t)g_csr_src[e] * 8];
#pragma unroll
            for (int k = 0; k < 8; k++) {
                float4 v = hr[k];
                hnf[4 * k + 0] = fmaxf(hnf[4 * k + 0], v.x);
                hnf[4 * k + 1] = fmaxf(hnf[4 * k + 1], v.y);
                hnf[4 * k + 2] = fmaxf(hnf[4 * k + 2], v.z);
                hnf[4 * k + 3] = fmaxf(hnf[4 * k + 3], v.w);
            }
        }
#pragma unroll
        for (int j = 0; j < 32; j++) stag[(32 + j) * STG + tid] = hnf[j];
    }
    __syncthreads();

    int og = tid >> 6;   // output group: 16 outputs (8 pairs) starting at og*16
    int nt = tid & 63;   // node set {nt, nt+64, nt+128, nt+192}

    // ---- h2 = relu(af@Wself + hnf@Wneigh + bneigh) ----
    u64 acc[4][8];
#pragma unroll
    for (int m = 0; m < 4; m++)
#pragma unroll
        for (int p = 0; p < 8; p++) acc[m][p] = sbn[og * 8 + p];
#pragma unroll
    for (int k = 0; k < 32; k++) {
        u64 a[4], b[4];
#pragma unroll
        for (int m = 0; m < 4; m++) {
            a[m] = pack2(stag[k * STG + nt + 64 * m]);
            b[m] = pack2(stag[(32 + k) * STG + nt + 64 * m]);
        }
        const ulonglong2* ps = (const ulonglong2*)&sWs[k * 32 + og * 8];
        const ulonglong2* pn = (const ulonglong2*)&sWn[k * 32 + og * 8];
#pragma unroll
        for (int jj = 0; jj < 4; jj++) {
            ulonglong2 w = ps[jj];
            ulonglong2 u = pn[jj];
#pragma unroll
            for (int m = 0; m < 4; m++) {
                fma2(acc[m][2 * jj], a[m], w.x);
                fma2(acc[m][2 * jj + 1], a[m], w.y);
                fma2(acc[m][2 * jj], b[m], u.x);
                fma2(acc[m][2 * jj + 1], b[m], u.y);
            }
        }
    }
    __syncthreads();   // all reads of channels 0..63 done before overwrite
#pragma unroll
    for (int m = 0; m < 4; m++)
#pragma unroll
        for (int p = 0; p < 8; p++) {
            float2 f = unpack2(acc[m][p]);
            stag[(og * 16 + 2 * p) * STG + nt + 64 * m]     = fmaxf(f.x, 0.f);
            stag[(og * 16 + 2 * p + 1) * STG + nt + 64 * m] = fmaxf(f.y, 0.f);
        }
    __syncthreads();

    // ---- h3 = relu(h2@Wlin + blin) ----
    u64 a2[4][8];
#pragma unroll
    for (int m = 0; m < 4; m++)
#pragma unroll
        for (int p = 0; p < 8; p++) a2[m][p] = sbl[og * 8 + p];
#pragma unroll
    for (int k2 = 0; k2 < 64; k2++) {
        u64 a[4];
#pragma unroll
        for (int m = 0; m < 4; m++) a[m] = pack2(stag[k2 * STG + nt + 64 * m]);
        const ulonglong2* pl = (const ulonglong2*)&sWl[k2 * 32 + og * 8];
#pragma unroll
        for (int jj = 0; jj < 4; jj++) {
            ulonglong2 w = pl[jj];
#pragma unroll
            for (int m = 0; m < 4; m++) {
                fma2(a2[m][2 * jj], a[m], w.x);
                fma2(a2[m][2 * jj + 1], a[m], w.y);
            }
        }
    }
    __syncthreads();
#pragma unroll
    for (int m = 0; m < 4; m++)
#pragma unroll
        for (int p = 0; p < 8; p++) {
            float2 f = unpack2(a2[m][p]);
            stag[(og * 16 + 2 * p) * STG + nt + 64 * m]     = fmaxf(f.x, 0.f);
            stag[(og * 16 + 2 * p + 1) * STG + nt + 64 * m] = fmaxf(f.y, 0.f);
        }
    __syncthreads();

    // ---- pooling: run-based sum over this quarter's 64 slots ----
    {
        int c = tid & 63;    // channel
        int q = tid >> 6;    // quarter
        float run = 0.f;
        int cur = -1;
        for (int s = 0; s < 64; s++) {
            int slot = q * 64 + s;
            int g = sgid[slot];
            float v = stag[c * STG + slot];
            if (g != cur) {
                if (cur >= 0) atomicAdd(out + cur * 64 + c, run);
                run = 0.f;
                cur = g;
            }
            if (g >= 0) run += v;
        }
        if (cur >= 0) atomicAdd(out + cur * 64 + c, run);
    }
}

// ---------------- launch ----------------
extern "C" void kernel_launch(void* const* d_in, const int* in_sizes, int n_in,
                              void* d_out, int out_size) {
    const int*   tokens    = (const int*)  d_in[0];
    const int*   edge_src  = (const int*)  d_in[1];
    const int*   edge_dst  = (const int*)  d_in[2];
    const int*   graph_ids = (const int*)  d_in[3];
    const float* embed     = (const float*)d_in[4];
    const float* W1        = (const float*)d_in[5];
    const float* b1        = (const float*)d_in[6];
    const float* Wpool     = (const float*)d_in[7];
    const float* bpool     = (const float*)d_in[8];
    const float* Wself     = (const float*)d_in[9];
    const float* Wneigh    = (const float*)d_in[10];
    const float* bneigh    = (const float*)d_in[11];
    const float* Wlin      = (const float*)d_in[12];
    const float* blin      = (const float*)d_in[13];
    float* out = (float*)d_out;

    cudaFuncSetAttribute(k_out, cudaFuncAttributeMaxDynamicSharedMemorySize, STAG_BYTES);

    const int TB = 256;
    int gridE = (NE + TB - 1) / TB;
    int gridN = (NN + TB - 1) / TB;
    int gridO = (NN + 255) / 256;

    k_init<<<gridN, TB>>>(out);
    k_deg<<<gridE, TB>>>(edge_src, edge_dst);
    k_scan_bsum <<<SCAN_NBLK, SCAN_BS>>>();
    k_scan_top  <<<1, SCAN_BS>>>();
    k_scan_write<<<SCAN_NBLK, SCAN_BS>>>();
    k_fill<<<gridE, TB>>>(edge_src, edge_dst, tokens);
    k_h1<<<gridN, TB>>>(embed, W1, b1, Wpool, bpool);
    k_out<<<gridO, TB, STAG_BYTES>>>(graph_ids, Wself, Wneigh, bneigh, Wlin, blin, out);
}

// round 15
// speedup vs baseline: 1.5695x; 1.0258x over previous
#include <cuda_runtime.h>

#define NN 500000
#define NE 1000000
#define NG 512

#define SCAN_BS 256
#define SCAN_ELEMS 2048                       // 256 threads * 8
#define SCAN_NBLK ((NN + SCAN_ELEMS - 1) / SCAN_ELEMS)   // 245

#define STG 257                                // staging stride (bank-conflict pad)
#define STAG_BYTES (64 * STG * 4)

typedef unsigned long long u64;

// ---------------- scratch ----------------
__device__ int    g_cnt_out[NN];
__device__ int    g_cnt_in [NN];
__device__ float  g_ns     [NN];   // rsqrt(max(deg_out,1))
__device__ int    g_row_off[NN + 1];
__device__ int    g_cursor [NN];
__device__ int    g_csr_src[NE];
__device__ int    g_bsum [256];
__device__ int    g_bpref[256];
__device__ float4 g_h1[NN * 8];    // [N,32]
__device__ float4 g_hp[NN * 8];    // [N,32] relu(h1@Wpool+bpool)

// ---------------- f32x2 helpers ----------------
__device__ __forceinline__ u64 pack2(float a) {
    u64 r;
    asm("mov.b64 %0, {%1, %1};" : "=l"(r) : "f"(a));
    return r;
}
__device__ __forceinline__ void fma2(u64& d, u64 a, u64 b) {
    asm("fma.rn.f32x2 %0, %1, %2, %0;" : "+l"(d) : "l"(a), "l"(b));
}
__device__ __forceinline__ float2 unpack2(u64 v) {
    float2 f;
    asm("mov.b64 {%0, %1}, %2;" : "=f"(f.x), "=f"(f.y) : "l"(v));
    return f;
}

// ---------------- init ----------------
__global__ void k_init(float* __restrict__ out) {
    int i = blockIdx.x * blockDim.x + threadIdx.x;
    if (i < NN) { g_cnt_out[i] = 0; g_cnt_in[i] = 0; }
    if (i < NG * 64) out[i] = 0.f;
}

// ---------------- degree counts ----------------
__global__ void k_deg(const int* __restrict__ src, const int* __restrict__ dst) {
    int e = blockIdx.x * blockDim.x + threadIdx.x;
    if (e < NE) {
        atomicAdd(&g_cnt_out[src[e]], 1);
        atomicAdd(&g_cnt_in [dst[e]], 1);
    }
}

// ---------------- scan pass 1 ----------------
__global__ __launch_bounds__(SCAN_BS) void k_scan_bsum() {
    __shared__ int sred[SCAN_BS];
    int b = blockIdx.x, t = threadIdx.x;
    int base = b * SCAN_ELEMS + t * 8;
    int s = 0;
#pragma unroll
    for (int k = 0; k < 8; k++) {
        int idx = base + k;
        if (idx < NN) s += g_cnt_in[idx];
    }
    sred[t] = s;
    __syncthreads();
    for (int o = SCAN_BS / 2; o > 0; o >>= 1) {
        if (t < o) sred[t] += sred[t + o];
        __syncthreads();
    }
    if (t == 0) g_bsum[b] = sred[0];
}

// ---------------- scan pass 2 ----------------
__global__ __launch_bounds__(SCAN_BS) void k_scan_top() {
    __shared__ int s[SCAN_BS];
    int t = threadIdx.x;
    int v = (t < SCAN_NBLK) ? g_bsum[t] : 0;
    s[t] = v;
    __syncthreads();
    for (int o = 1; o < SCAN_BS; o <<= 1) {
        int u = (t >= o) ? s[t - o] : 0;
        __syncthreads();
        s[t] += u;
        __syncthreads();
    }
    if (t < SCAN_NBLK) g_bpref[t] = s[t] - v;
    if (t == 0) g_row_off[NN] = NE;
}

// ---------------- scan pass 3 (also computes g_ns) ----------------
__global__ __launch_bounds__(SCAN_BS) void k_scan_write() {
    __shared__ int sth[SCAN_BS];
    int b = blockIdx.x, t = threadIdx.x;
    int base = b * SCAN_ELEMS + t * 8;
    int vals[8];
    int s = 0;
#pragma unroll
    for (int k = 0; k < 8; k++) {
        int idx = base + k;
        vals[k] = (idx < NN) ? g_cnt_in[idx] : 0;
        s += vals[k];
    }
    sth[t] = s;
    __syncthreads();
    int incl = s;
    for (int o = 1; o < SCAN_BS; o <<= 1) {
        int u = (t >= o) ? sth[t - o] : 0;
        __syncthreads();
        incl += u;
        sth[t] = incl;
        __syncthreads();
    }
    int run = g_bpref[b] + incl - s;
#pragma unroll
    for (int k = 0; k < 8; k++) {
        int idx = base + k;
        if (idx < NN) {
            g_row_off[idx] = run;
            g_cursor[idx] = run;
            g_ns[idx] = rsqrtf(fmaxf((float)g_cnt_out[idx], 1.0f));
        }
        run += vals[k];
    }
}

// ---------------- CSR fill ----------------
__global__ void k_fill(const int* __restrict__ src, const int* __restrict__ dst) {
    int e = blockIdx.x * blockDim.x + threadIdx.x;
    if (e < NE) {
        int p = atomicAdd(&g_cursor[dst[e]], 1);
        g_csr_src[p] = src[e];
    }
}

// ---------------- gather embed + MLP1 + pool MLP ----------------
__global__ __launch_bounds__(256) void k_h1(
    const int* __restrict__ tokens, const float* __restrict__ embed,
    const float* __restrict__ W1, const float* __restrict__ b1,
    const float* __restrict__ Wp, const float* __restrict__ bp)
{
    __shared__ __align__(16) u64 sW1[16 * 16], sWp[32 * 16];
    __shared__ u64 sb1[16], sbp[16];
    for (int t = threadIdx.x; t < 16 * 16; t += blockDim.x)
        ((float2*)sW1)[t] = ((const float2*)W1)[t];
    for (int t = threadIdx.x; t < 32 * 16; t += blockDim.x)
        ((float2*)sWp)[t] = ((const float2*)Wp)[t];
    for (int t = threadIdx.x; t < 16; t += blockDim.x) {
        ((float2*)sb1)[t] = ((const float2*)b1)[t];
        ((float2*)sbp)[t] = ((const float2*)bp)[t];
    }
    __syncthreads();

    int i = blockIdx.x * blockDim.x + threadIdx.x;
    if (i >= NN) return;

    int beg = g_row_off[i], end = g_row_off[i + 1];
    float4 a0 = make_float4(0, 0, 0, 0), a1 = a0, a2 = a0, a3 = a0;
    for (int e = beg; e < end; e++) {
        int s = g_csr_src[e];
        float ns = g_ns[s];
        const float4* er = (const float4*)(embed + (long)tokens[s] * 16);
        float4 v0 = er[0], v1 = er[1], v2 = er[2], v3 = er[3];
        a0.x += v0.x * ns; a0.y += v0.y * ns; a0.z += v0.z * ns; a0.w += v0.w * ns;
        a1.x += v1.x * ns; a1.y += v1.y * ns; a1.z += v1.z * ns; a1.w += v1.w * ns;
        a2.x += v2.x * ns; a2.y += v2.y * ns; a2.z += v2.z * ns; a2.w += v2.w * ns;
        a3.x += v3.x * ns; a3.y += v3.y * ns; a3.z += v3.z * ns; a3.w += v3.w * ns;
    }
    float nd = rsqrtf(fmaxf((float)(end - beg), 1.0f));
    float mr[16] = {a0.x * nd, a0.y * nd, a0.z * nd, a0.w * nd,
                    a1.x * nd, a1.y * nd, a1.z * nd, a1.w * nd,
                    a2.x * nd, a2.y * nd, a2.z * nd, a2.w * nd,
                    a3.x * nd, a3.y * nd, a3.z * nd, a3.w * nd};

    // h1 = relu(mr @ W1 + b1)
    u64 acc[16];
#pragma unroll
    for (int j = 0; j < 16; j++) acc[j] = sb1[j];
#pragma unroll
    for (int k = 0; k < 16; k++) {
        u64 av = pack2(mr[k]);
        const ulonglong2* pw = (const ulonglong2*)&sW1[k * 16];
#pragma unroll
        for (int jj = 0; jj < 8; jj++) {
            ulonglong2 w = pw[jj];
            fma2(acc[2 * jj], av, w.x);
            fma2(acc[2 * jj + 1], av, w.y);
        }
    }
    float h1f[32];
#pragma unroll
    for (int j = 0; j < 16; j++) {
        float2 f = unpack2(acc[j]);
        h1f[2 * j] = fmaxf(f.x, 0.f); h1f[2 * j + 1] = fmaxf(f.y, 0.f);
    }
#pragma unroll
    for (int k = 0; k < 8; k++)
        g_h1[i * 8 + k] = make_float4(h1f[4 * k], h1f[4 * k + 1], h1f[4 * k + 2], h1f[4 * k + 3]);

    // hp = relu(h1 @ Wpool + bpool)
    u64 pcc[16];
#pragma unroll
    for (int j = 0; j < 16; j++) pcc[j] = sbp[j];
#pragma unroll
    for (int k = 0; k < 32; k++) {
        u64 av = pack2(h1f[k]);
        const ulonglong2* pw = (const ulonglong2*)&sWp[k * 16];
#pragma unroll
        for (int jj = 0; jj < 8; jj++) {
            ulonglong2 w = pw[jj];
            fma2(pcc[2 * jj], av, w.x);
            fma2(pcc[2 * jj + 1], av, w.y);
        }
    }
#pragma unroll
    for (int j = 0; j < 8; j++) {
        float2 f0 = unpack2(pcc[2 * j]), f1 = unpack2(pcc[2 * j + 1]);
        g_hp[i * 8 + j] = make_float4(fmaxf(f0.x, 0.f), fmaxf(f0.y, 0.f),
                                      fmaxf(f1.x, 0.f), fmaxf(f1.y, 0.f));
    }
}

// ---------------- fused: gather-max + SAGE + lin + pooling ----------------
// Block = 256 nodes staged in smem (stride-257, conflict-free).
// Gather phase: 1 node/thread. Compute phases: thread = 16 outputs x 4 nodes.
// Pooling: thread = channel x quarter, run-based sum with per-slot graph ids.
__global__ __launch_bounds__(256, 2) void k_out(
    const int* __restrict__ graph_ids,
    const float* __restrict__ Wself, const float* __restrict__ Wneigh,
    const float* __restrict__ bneigh,
    const float* __restrict__ Wlin, const float* __restrict__ blin,
    float* __restrict__ out)
{
    __shared__ __align__(16) u64 sWs[32 * 32], sWn[32 * 32], sWl[64 * 32];
    __shared__ u64 sbn[32], sbl[32];
    __shared__ int sgid[256];
    extern __shared__ float stag[];   // 64 * STG floats

    for (int t = threadIdx.x; t < 32 * 32; t += blockDim.x) {
        ((float2*)sWs)[t] = ((const float2*)Wself)[t];
        ((float2*)sWn)[t] = ((const float2*)Wneigh)[t];
    }
    for (int t = threadIdx.x; t < 64 * 32; t += blockDim.x)
        ((float2*)sWl)[t] = ((const float2*)Wlin)[t];
    for (int t = threadIdx.x; t < 32; t += blockDim.x) {
        ((float2*)sbn)[t] = ((const float2*)bneigh)[t];
        ((float2*)sbl)[t] = ((const float2*)blin)[t];
    }

    int tid = threadIdx.x;
    int i = blockIdx.x * 256 + tid;
    bool valid = i < NN;
    int ic = valid ? i : NN - 1;
    sgid[tid] = valid ? graph_ids[ic] : -1;

    // ---- gather phase: 1 node/thread ----
#pragma unroll
    for (int k = 0; k < 8; k++) {
        float4 v = g_h1[(size_t)ic * 8 + k];
        stag[(4 * k + 0) * STG + tid] = v.x;
        stag[(4 * k + 1) * STG + tid] = v.y;
        stag[(4 * k + 2) * STG + tid] = v.z;
        stag[(4 * k + 3) * STG + tid] = v.w;
    }
    {
        float hnf[32];
#pragma unroll
        for (int j = 0; j < 32; j++) hnf[j] = 0.f;
        int beg = g_row_off[ic], end = g_row_off[ic + 1];
        for (int e = beg; e < end; e++) {
            const float4* hr = &g_hp[(size_t)g_csr_src[e] * 8];
#pragma unroll
            for (int k = 0; k < 8; k++) {
                float4 v = hr[k];
                hnf[4 * k + 0] = fmaxf(hnf[4 * k + 0], v.x);
                hnf[4 * k + 1] = fmaxf(hnf[4 * k + 1], v.y);
                hnf[4 * k + 2] = fmaxf(hnf[4 * k + 2], v.z);
                hnf[4 * k + 3] = fmaxf(hnf[4 * k + 3], v.w);
            }
        }
#pragma unroll
        for (int j = 0; j < 32; j++) stag[(32 + j) * STG + tid] = hnf[j];
    }
    __syncthreads();

    int og = tid >> 6;   // output group: 16 outputs (8 pairs) starting at og*16
    int nt = tid & 63;   // node set {nt, nt+64, nt+128, nt+192}

    // ---- h2 = relu(af@Wself + hnf@Wneigh + bneigh) ----
    u64 acc[4][8];
#pragma unroll
    for (int m = 0; m < 4; m++)
#pragma unroll
        for (int p = 0; p < 8; p++) acc[m][p] = sbn[og * 8 + p];
#pragma unroll
    for (int k = 0; k < 32; k++) {
        u64 a[4], b[4];
#pragma unroll
        for (int m = 0; m < 4; m++) {
            a[m] = pack2(stag[k * STG + nt + 64 * m]);
            b[m] = pack2(stag[(32 + k) * STG + nt + 64 * m]);
        }
        const ulonglong2* ps = (const ulonglong2*)&sWs[k * 32 + og * 8];
        const ulonglong2* pn = (const ulonglong2*)&sWn[k * 32 + og * 8];
#pragma unroll
        for (int jj = 0; jj < 4; jj++) {
            ulonglong2 w = ps[jj];
            ulonglong2 u = pn[jj];
#pragma unroll
            for (int m = 0; m < 4; m++) {
                fma2(acc[m][2 * jj], a[m], w.x);
                fma2(acc[m][2 * jj + 1], a[m], w.y);
                fma2(acc[m][2 * jj], b[m], u.x);
                fma2(acc[m][2 * jj + 1], b[m], u.y);
            }
        }
    }
    __syncthreads();   // all reads of channels 0..63 done before overwrite
#pragma unroll
    for (int m = 0; m < 4; m++)
#pragma unroll
        for (int p = 0; p < 8; p++) {
            float2 f = unpack2(acc[m][p]);
            stag[(og * 16 + 2 * p) * STG + nt + 64 * m]     = fmaxf(f.x, 0.f);
            stag[(og * 16 + 2 * p + 1) * STG + nt + 64 * m] = fmaxf(f.y, 0.f);
        }
    __syncthreads();

    // ---- h3 = relu(h2@Wlin + blin) ----
    u64 a2[4][8];
#pragma unroll
    for (int m = 0; m < 4; m++)
#pragma unroll
        for (int p = 0; p < 8; p++) a2[m][p] = sbl[og * 8 + p];
#pragma unroll
    for (int k2 = 0; k2 < 64; k2++) {
        u64 a[4];
#pragma unroll
        for (int m = 0; m < 4; m++) a[m] = pack2(stag[k2 * STG + nt + 64 * m]);
        const ulonglong2* pl = (const ulonglong2*)&sWl[k2 * 32 + og * 8];
#pragma unroll
        for (int jj = 0; jj < 4; jj++) {
            ulonglong2 w = pl[jj];
#pragma unroll
            for (int m = 0; m < 4; m++) {
                fma2(a2[m][2 * jj], a[m], w.x);
                fma2(a2[m][2 * jj + 1], a[m], w.y);
            }
        }
    }
    __syncthreads();
#pragma unroll
    for (int m = 0; m < 4; m++)
#pragma unroll
        for (int p = 0; p < 8; p++) {
            float2 f = unpack2(a2[m][p]);
            stag[(og * 16 + 2 * p) * STG + nt + 64 * m]     = fmaxf(f.x, 0.f);
            stag[(og * 16 + 2 * p + 1) * STG + nt + 64 * m] = fmaxf(f.y, 0.f);
        }
    __syncthreads();

    // ---- pooling: run-based sum over this quarter's 64 slots ----
    {
        int c = tid & 63;    // channel
        int q = tid >> 6;    // quarter
        float run = 0.f;
        int cur = -1;
        for (int s = 0; s < 64; s++) {
            int slot = q * 64 + s;
            int g = sgid[slot];
            float v = stag[c * STG + slot];
            if (g != cur) {
                if (cur >= 0) atomicAdd(out + cur * 64 + c, run);
                run = 0.f;
                cur = g;
            }
            if (g >= 0) run += v;
        }
        if (cur >= 0) atomicAdd(out + cur * 64 + c, run);
    }
}

// ---------------- launch ----------------
extern "C" void kernel_launch(void* const* d_in, const int* in_sizes, int n_in,
                              void* d_out, int out_size) {
    const int*   tokens    = (const int*)  d_in[0];
    const int*   edge_src  = (const int*)  d_in[1];
    const int*   edge_dst  = (const int*)  d_in[2];
    const int*   graph_ids = (const int*)  d_in[3];
    const float* embed     = (const float*)d_in[4];
    const float* W1        = (const float*)d_in[5];
    const float* b1        = (const float*)d_in[6];
    const float* Wpool     = (const float*)d_in[7];
    const float* bpool     = (const float*)d_in[8];
    const float* Wself     = (const float*)d_in[9];
    const float* Wneigh    = (const float*)d_in[10];
    const float* bneigh    = (const float*)d_in[11];
    const float* Wlin      = (const float*)d_in[12];
    const float* blin      = (const float*)d_in[13];
    float* out = (float*)d_out;

    cudaFuncSetAttribute(k_out, cudaFuncAttributeMaxDynamicSharedMemorySize, STAG_BYTES);

    const int TB = 256;
    int gridE = (NE + TB - 1) / TB;
    int gridN = (NN + TB - 1) / TB;
    int gridO = (NN + 255) / 256;

    k_init<<<gridN, TB>>>(out);
    k_deg<<<gridE, TB>>>(edge_src, edge_dst);
    k_scan_bsum <<<SCAN_NBLK, SCAN_BS>>>();
    k_scan_top  <<<1, SCAN_BS>>>();
    k_scan_write<<<SCAN_NBLK, SCAN_BS>>>();
    k_fill<<<gridE, TB>>>(edge_src, edge_dst);
    k_h1<<<gridN, TB>>>(tokens, embed, W1, b1, Wpool, bpool);
    k_out<<<gridO, TB, STAG_BYTES>>>(graph_ids, Wself, Wneigh, bneigh, Wlin, blin, out);
}

// round 16
// speedup vs baseline: 1.5880x; 1.0118x over previous
#include <cuda_runtime.h>

#define NN 500000
#define NE 1000000
#define NG 512

#define SCAN_BS 256
#define SCAN_ELEMS 2048                       // 256 threads * 8
#define SCAN_NBLK ((NN + SCAN_ELEMS - 1) / SCAN_ELEMS)   // 245

#define STG 257                                // staging stride (bank-conflict pad)
#define STAG_BYTES (64 * STG * 4)

typedef unsigned long long u64;

// ---------------- scratch ----------------
__device__ int    g_cnt_out[NN];
__device__ int    g_cnt_in [NN];
__device__ float  g_ns     [NN];   // rsqrt(max(deg_out,1))
__device__ int    g_row_off[NN + 1];
__device__ int    g_cursor [NN];
__device__ int    g_csr_src[NE];
__device__ int    g_bsum [256];
__device__ int    g_bpref[256];
__device__ float4 g_h1[NN * 8];    // [N,32]
__device__ float4 g_hp[NN * 8];    // [N,32] relu(h1@Wpool+bpool)

// ---------------- f32x2 helpers ----------------
__device__ __forceinline__ u64 pack2(float a) {
    u64 r;
    asm("mov.b64 %0, {%1, %1};" : "=l"(r) : "f"(a));
    return r;
}
__device__ __forceinline__ void fma2(u64& d, u64 a, u64 b) {
    asm("fma.rn.f32x2 %0, %1, %2, %0;" : "+l"(d) : "l"(a), "l"(b));
}
__device__ __forceinline__ float2 unpack2(u64 v) {
    float2 f;
    asm("mov.b64 {%0, %1}, %2;" : "=f"(f.x), "=f"(f.y) : "l"(v));
    return f;
}

// ---------------- init ----------------
__global__ void k_init(float* __restrict__ out) {
    int i = blockIdx.x * blockDim.x + threadIdx.x;
    if (i < NN) { g_cnt_out[i] = 0; g_cnt_in[i] = 0; }
    if (i < NG * 64) out[i] = 0.f;
}

// ---------------- degree counts ----------------
__global__ void k_deg(const int* __restrict__ src, const int* __restrict__ dst) {
    int e = blockIdx.x * blockDim.x + threadIdx.x;
    if (e < NE) {
        atomicAdd(&g_cnt_out[src[e]], 1);
        atomicAdd(&g_cnt_in [dst[e]], 1);
    }
}

// ---------------- scan pass 1 ----------------
__global__ __launch_bounds__(SCAN_BS) void k_scan_bsum() {
    __shared__ int sred[SCAN_BS];
    int b = blockIdx.x, t = threadIdx.x;
    int base = b * SCAN_ELEMS + t * 8;
    int s = 0;
#pragma unroll
    for (int k = 0; k < 8; k++) {
        int idx = base + k;
        if (idx < NN) s += g_cnt_in[idx];
    }
    sred[t] = s;
    __syncthreads();
    for (int o = SCAN_BS / 2; o > 0; o >>= 1) {
        if (t < o) sred[t] += sred[t + o];
        __syncthreads();
    }
    if (t == 0) g_bsum[b] = sred[0];
}

// ---------------- scan pass 2 ----------------
__global__ __launch_bounds__(SCAN_BS) void k_scan_top() {
    __shared__ int s[SCAN_BS];
    int t = threadIdx.x;
    int v = (t < SCAN_NBLK) ? g_bsum[t] : 0;
    s[t] = v;
    __syncthreads();
    for (int o = 1; o < SCAN_BS; o <<= 1) {
        int u = (t >= o) ? s[t - o] : 0;
        __syncthreads();
        s[t] += u;
        __syncthreads();
    }
    if (t < SCAN_NBLK) g_bpref[t] = s[t] - v;
    if (t == 0) g_row_off[NN] = NE;
}

// ---------------- scan pass 3 (also computes g_ns) ----------------
__global__ __launch_bounds__(SCAN_BS) void k_scan_write() {
    __shared__ int sth[SCAN_BS];
    int b = blockIdx.x, t = threadIdx.x;
    int base = b * SCAN_ELEMS + t * 8;
    int vals[8];
    int s = 0;
#pragma unroll
    for (int k = 0; k < 8; k++) {
        int idx = base + k;
        vals[k] = (idx < NN) ? g_cnt_in[idx] : 0;
        s += vals[k];
    }
    sth[t] = s;
    __syncthreads();
    int incl = s;
    for (int o = 1; o < SCAN_BS; o <<= 1) {
        int u = (t >= o) ? sth[t - o] : 0;
        __syncthreads();
        incl += u;
        sth[t] = incl;
        __syncthreads();
    }
    int run = g_bpref[b] + incl - s;
#pragma unroll
    for (int k = 0; k < 8; k++) {
        int idx = base + k;
        if (idx < NN) {
            g_row_off[idx] = run;
            g_cursor[idx] = run;
            g_ns[idx] = rsqrtf(fmaxf((float)g_cnt_out[idx], 1.0f));
        }
        run += vals[k];
    }
}

// ---------------- CSR fill ----------------
__global__ void k_fill(const int* __restrict__ src, const int* __restrict__ dst) {
    int e = blockIdx.x * blockDim.x + threadIdx.x;
    if (e < NE) {
        int p = atomicAdd(&g_cursor[dst[e]], 1);
        g_csr_src[p] = src[e];
    }
}

// ---------------- gather embed + MLP1 + pool MLP ----------------
// __launch_bounds__(256, 3): force <=85 regs -> 3 CTAs/SM (24 warps) for the
// latency-bound gather (R11 probe: issue 20.7% at 16 warps, regs 87).
__global__ __launch_bounds__(256, 3) void k_h1(
    const int* __restrict__ tokens, const float* __restrict__ embed,
    const float* __restrict__ W1, const float* __restrict__ b1,
    const float* __restrict__ Wp, const float* __restrict__ bp)
{
    __shared__ __align__(16) u64 sW1[16 * 16], sWp[32 * 16];
    __shared__ u64 sb1[16], sbp[16];
    for (int t = threadIdx.x; t < 16 * 16; t += blockDim.x)
        ((float2*)sW1)[t] = ((const float2*)W1)[t];
    for (int t = threadIdx.x; t < 32 * 16; t += blockDim.x)
        ((float2*)sWp)[t] = ((const float2*)Wp)[t];
    for (int t = threadIdx.x; t < 16; t += blockDim.x) {
        ((float2*)sb1)[t] = ((const float2*)b1)[t];
        ((float2*)sbp)[t] = ((const float2*)bp)[t];
    }
    __syncthreads();

    int i = blockIdx.x * blockDim.x + threadIdx.x;
    if (i >= NN) return;

    int beg = g_row_off[i], end = g_row_off[i + 1];
    float4 a0 = make_float4(0, 0, 0, 0), a1 = a0, a2 = a0, a3 = a0;
    for (int e = beg; e < end; e++) {
        int s = g_csr_src[e];
        float ns = g_ns[s];
        const float4* er = (const float4*)(embed + (long)tokens[s] * 16);
        float4 v0 = er[0], v1 = er[1], v2 = er[2], v3 = er[3];
        a0.x += v0.x * ns; a0.y += v0.y * ns; a0.z += v0.z * ns; a0.w += v0.w * ns;
        a1.x += v1.x * ns; a1.y += v1.y * ns; a1.z += v1.z * ns; a1.w += v1.w * ns;
        a2.x += v2.x * ns; a2.y += v2.y * ns; a2.z += v2.z * ns; a2.w += v2.w * ns;
        a3.x += v3.x * ns; a3.y += v3.y * ns; a3.z += v3.z * ns; a3.w += v3.w * ns;
    }
    float nd = rsqrtf(fmaxf((float)(end - beg), 1.0f));
    float mr[16] = {a0.x * nd, a0.y * nd, a0.z * nd, a0.w * nd,
                    a1.x * nd, a1.y * nd, a1.z * nd, a1.w * nd,
                    a2.x * nd, a2.y * nd, a2.z * nd, a2.w * nd,
                    a3.x * nd, a3.y * nd, a3.z * nd, a3.w * nd};

    // h1 = relu(mr @ W1 + b1)
    u64 acc[16];
#pragma unroll
    for (int j = 0; j < 16; j++) acc[j] = sb1[j];
#pragma unroll
    for (int k = 0; k < 16; k++) {
        u64 av = pack2(mr[k]);
        const ulonglong2* pw = (const ulonglong2*)&sW1[k * 16];
#pragma unroll
        for (int jj = 0; jj < 8; jj++) {
            ulonglong2 w = pw[jj];
            fma2(acc[2 * jj], av, w.x);
            fma2(acc[2 * jj + 1], av, w.y);
        }
    }
    float h1f[32];
#pragma unroll
    for (int j = 0; j < 16; j++) {
        float2 f = unpack2(acc[j]);
        h1f[2 * j] = fmaxf(f.x, 0.f); h1f[2 * j + 1] = fmaxf(f.y, 0.f);
    }
#pragma unroll
    for (int k = 0; k < 8; k++)
        g_h1[i * 8 + k] = make_float4(h1f[4 * k], h1f[4 * k + 1], h1f[4 * k + 2], h1f[4 * k + 3]);

    // hp = relu(h1 @ Wpool + bpool)
    u64 pcc[16];
#pragma unroll
    for (int j = 0; j < 16; j++) pcc[j] = sbp[j];
#pragma unroll
    for (int k = 0; k < 32; k++) {
        u64 av = pack2(h1f[k]);
        const ulonglong2* pw = (const ulonglong2*)&sWp[k * 16];
#pragma unroll
        for (int jj = 0; jj < 8; jj++) {
            ulonglong2 w = pw[jj];
            fma2(pcc[2 * jj], av, w.x);
            fma2(pcc[2 * jj + 1], av, w.y);
        }
    }
#pragma unroll
    for (int j = 0; j < 8; j++) {
        float2 f0 = unpack2(pcc[2 * j]), f1 = unpack2(pcc[2 * j + 1]);
        g_hp[i * 8 + j] = make_float4(fmaxf(f0.x, 0.f), fmaxf(f0.y, 0.f),
                                      fmaxf(f1.x, 0.f), fmaxf(f1.y, 0.f));
    }
}

// ---------------- fused: gather-max + SAGE + lin + pooling ----------------
// Block = 256 nodes staged in smem (stride-257, conflict-free).
// Gather phase: 1 node/thread. Compute phases: thread = 16 outputs x 4 nodes.
// Pooling: thread = channel x quarter, run-based sum with per-slot graph ids.
__global__ __launch_bounds__(256, 2) void k_out(
    const int* __restrict__ graph_ids,
    const float* __restrict__ Wself, const float* __restrict__ Wneigh,
    const float* __restrict__ bneigh,
    const float* __restrict__ Wlin, const float* __restrict__ blin,
    float* __restrict__ out)
{
    __shared__ __align__(16) u64 sWs[32 * 32], sWn[32 * 32], sWl[64 * 32];
    __shared__ u64 sbn[32], sbl[32];
    __shared__ int sgid[256];
    extern __shared__ float stag[];   // 64 * STG floats

    for (int t = threadIdx.x; t < 32 * 32; t += blockDim.x) {
        ((float2*)sWs)[t] = ((const float2*)Wself)[t];
        ((float2*)sWn)[t] = ((const float2*)Wneigh)[t];
    }
    for (int t = threadIdx.x; t < 64 * 32; t += blockDim.x)
        ((float2*)sWl)[t] = ((const float2*)Wlin)[t];
    for (int t = threadIdx.x; t < 32; t += blockDim.x) {
        ((float2*)sbn)[t] = ((const float2*)bneigh)[t];
        ((float2*)sbl)[t] = ((const float2*)blin)[t];
    }

    int tid = threadIdx.x;
    int i = blockIdx.x * 256 + tid;
    bool valid = i < NN;
    int ic = valid ? i : NN - 1;
    sgid[tid] = valid ? graph_ids[ic] : -1;

    // ---- gather phase: 1 node/thread ----
#pragma unroll
    for (int k = 0; k < 8; k++) {
        float4 v = g_h1[(size_t)ic * 8 + k];
        stag[(4 * k + 0) * STG + tid] = v.x;
        stag[(4 * k + 1) * STG + tid] = v.y;
        stag[(4 * k + 2) * STG + tid] = v.z;
        stag[(4 * k + 3) * STG + tid] = v.w;
    }
    {
        float hnf[32];
#pragma unroll
        for (int j = 0; j < 32; j++) hnf[j] = 0.f;
        int beg = g_row_off[ic], end = g_row_off[ic + 1];
        for (int e = beg; e < end; e++) {
            const float4* hr = &g_hp[(size_t)g_csr_src[e] * 8];
#pragma unroll
            for (int k = 0; k < 8; k++) {
                float4 v = hr[k];
                hnf[4 * k + 0] = fmaxf(hnf[4 * k + 0], v.x);
                hnf[4 * k + 1] = fmaxf(hnf[4 * k + 1], v.y);
                hnf[4 * k + 2] = fmaxf(hnf[4 * k + 2], v.z);
                hnf[4 * k + 3] = fmaxf(hnf[4 * k + 3], v.w);
            }
        }
#pragma unroll
        for (int j = 0; j < 32; j++) stag[(32 + j) * STG + tid] = hnf[j];
    }
    __syncthreads();

    int og = tid >> 6;   // output group: 16 outputs (8 pairs) starting at og*16
    int nt = tid & 63;   // node set {nt, nt+64, nt+128, nt+192}

    // ---- h2 = relu(af@Wself + hnf@Wneigh + bneigh) ----
    u64 acc[4][8];
#pragma unroll
    for (int m = 0; m < 4; m++)
#pragma unroll
        for (int p = 0; p < 8; p++) acc[m][p] = sbn[og * 8 + p];
#pragma unroll
    for (int k = 0; k < 32; k++) {
        u64 a[4], b[4];
#pragma unroll
        for (int m = 0; m < 4; m++) {
            a[m] = pack2(stag[k * STG + nt + 64 * m]);
            b[m] = pack2(stag[(32 + k) * STG + nt + 64 * m]);
        }
        const ulonglong2* ps = (const ulonglong2*)&sWs[k * 32 + og * 8];
        const ulonglong2* pn = (const ulonglong2*)&sWn[k * 32 + og * 8];
#pragma unroll
        for (int jj = 0; jj < 4; jj++) {
            ulonglong2 w = ps[jj];
            ulonglong2 u = pn[jj];
#pragma unroll
            for (int m = 0; m < 4; m++) {
                fma2(acc[m][2 * jj], a[m], w.x);
                fma2(acc[m][2 * jj + 1], a[m], w.y);
                fma2(acc[m][2 * jj], b[m], u.x);
                fma2(acc[m][2 * jj + 1], b[m], u.y);
            }
        }
    }
    __syncthreads();   // all reads of channels 0..63 done before overwrite
#pragma unroll
    for (int m = 0; m < 4; m++)
#pragma unroll
        for (int p = 0; p < 8; p++) {
            float2 f = unpack2(acc[m][p]);
            stag[(og * 16 + 2 * p) * STG + nt + 64 * m]     = fmaxf(f.x, 0.f);
            stag[(og * 16 + 2 * p + 1) * STG + nt + 64 * m] = fmaxf(f.y, 0.f);
        }
    __syncthreads();

    // ---- h3 = relu(h2@Wlin + blin) ----
    u64 a2[4][8];
#pragma unroll
    for (int m = 0; m < 4; m++)
#pragma unroll
        for (int p = 0; p < 8; p++) a2[m][p] = sbl[og * 8 + p];
#pragma unroll
    for (int k2 = 0; k2 < 64; k2++) {
        u64 a[4];
#pragma unroll
        for (int m = 0; m < 4; m++) a[m] = pack2(stag[k2 * STG + nt + 64 * m]);
        const ulonglong2* pl = (const ulonglong2*)&sWl[k2 * 32 + og * 8];
#pragma unroll
        for (int jj = 0; jj < 4; jj++) {
            ulonglong2 w = pl[jj];
#pragma unroll
            for (int m = 0; m < 4; m++) {
                fma2(a2[m][2 * jj], a[m], w.x);
                fma2(a2[m][2 * jj + 1], a[m], w.y);
            }
        }
    }
    __syncthreads();
#pragma unroll
    for (int m = 0; m < 4; m++)
#pragma unroll
        for (int p = 0; p < 8; p++) {
            float2 f = unpack2(a2[m][p]);
            stag[(og * 16 + 2 * p) * STG + nt + 64 * m]     = fmaxf(f.x, 0.f);
            stag[(og * 16 + 2 * p + 1) * STG + nt + 64 * m] = fmaxf(f.y, 0.f);
        }
    __syncthreads();

    // ---- pooling: run-based sum over this quarter's 64 slots ----
    {
        int c = tid & 63;    // channel
        int q = tid >> 6;    // quarter
        float run = 0.f;
        int cur = -1;
        for (int s = 0; s < 64; s++) {
            int slot = q * 64 + s;
            int g = sgid[slot];
            float v = stag[c * STG + slot];
            if (g != cur) {
                if (cur >= 0) atomicAdd(out + cur * 64 + c, run);
                run = 0.f;
                cur = g;
            }
            if (g >= 0) run += v;
        }
        if (cur >= 0) atomicAdd(out + cur * 64 + c, run);
    }
}

// ---------------- launch ----------------
extern "C" void kernel_launch(void* const* d_in, const int* in_sizes, int n_in,
                              void* d_out, int out_size) {
    const int*   tokens    = (const int*)  d_in[0];
    const int*   edge_src  = (const int*)  d_in[1];
    const int*   edge_dst  = (const int*)  d_in[2];
    const int*   graph_ids = (const int*)  d_in[3];
    const float* embed     = (const float*)d_in[4];
    const float* W1        = (const float*)d_in[5];
    const float* b1        = (const float*)d_in[6];
    const float* Wpool     = (const float*)d_in[7];
    const float* bpool     = (const float*)d_in[8];
    const float* Wself     = (const float*)d_in[9];
    const float* Wneigh    = (const float*)d_in[10];
    const float* bneigh    = (const float*)d_in[11];
    const float* Wlin      = (const float*)d_in[12];
    const float* blin      = (const float*)d_in[13];
    float* out = (float*)d_out;

    cudaFuncSetAttribute(k_out, cudaFuncAttributeMaxDynamicSharedMemorySize, STAG_BYTES);

    const int TB = 256;
    int gridE = (NE + TB - 1) / TB;
    int gridN = (NN + TB - 1) / TB;
    int gridO = (NN + 255) / 256;

    k_init<<<gridN, TB>>>(out);
    k_deg<<<gridE, TB>>>(edge_src, edge_dst);
    k_scan_bsum <<<SCAN_NBLK, SCAN_BS>>>();
    k_scan_top  <<<1, SCAN_BS>>>();
    k_scan_write<<<SCAN_NBLK, SCAN_BS>>>();
    k_fill<<<gridE, TB>>>(edge_src, edge_dst);
    k_h1<<<gridN, TB>>>(tokens, embed, W1, b1, Wpool, bpool);
    k_out<<<gridO, TB, STAG_BYTES>>>(graph_ids, Wself, Wneigh, bneigh, Wlin, blin, out);
}

// round 17
// speedup vs baseline: 1.6290x; 1.0258x over previous
#include <cuda_runtime.h>

#define NN 500000
#define NE 1000000
#define NG 512

#define SCAN_BS 256
#define SCAN_ELEMS 2048                       // 256 threads * 8
#define SCAN_NBLK ((NN + SCAN_ELEMS - 1) / SCAN_ELEMS)   // 245

#define SROW 17                               // float4 per node row (64ch + pad)
#define STAG_BYTES (256 * SROW * 16)          // 69632 B

typedef unsigned long long u64;

// ---------------- scratch ----------------
__device__ int    g_cnt_out[NN];
__device__ int    g_cnt_in [NN];
__device__ float  g_ns     [NN];   // rsqrt(max(deg_out,1))
__device__ int    g_row_off[NN + 1];
__device__ int    g_cursor [NN];
__device__ int    g_csr_src[NE];
__device__ int    g_bsum [256];
__device__ int    g_bpref[256];
__device__ float4 g_h1[NN * 8];    // [N,32]
__device__ float4 g_hp[NN * 8];    // [N,32] relu(h1@Wpool+bpool)

// ---------------- f32x2 helpers ----------------
__device__ __forceinline__ u64 pack2(float a) {
    u64 r;
    asm("mov.b64 %0, {%1, %1};" : "=l"(r) : "f"(a));
    return r;
}
__device__ __forceinline__ void fma2(u64& d, u64 a, u64 b) {
    asm("fma.rn.f32x2 %0, %1, %2, %0;" : "+l"(d) : "l"(a), "l"(b));
}
__device__ __forceinline__ float2 unpack2(u64 v) {
    float2 f;
    asm("mov.b64 {%0, %1}, %2;" : "=f"(f.x), "=f"(f.y) : "l"(v));
    return f;
}

// ---------------- init ----------------
__global__ void k_init(float* __restrict__ out) {
    int i = blockIdx.x * blockDim.x + threadIdx.x;
    if (i < NN) { g_cnt_out[i] = 0; g_cnt_in[i] = 0; }
    if (i < NG * 64) out[i] = 0.f;
}

// ---------------- degree counts ----------------
__global__ void k_deg(const int* __restrict__ src, const int* __restrict__ dst) {
    int e = blockIdx.x * blockDim.x + threadIdx.x;
    if (e < NE) {
        atomicAdd(&g_cnt_out[src[e]], 1);
        atomicAdd(&g_cnt_in [dst[e]], 1);
    }
}

// ---------------- scan pass 1 ----------------
__global__ __launch_bounds__(SCAN_BS) void k_scan_bsum() {
    __shared__ int sred[SCAN_BS];
    int b = blockIdx.x, t = threadIdx.x;
    int base = b * SCAN_ELEMS + t * 8;
    int s = 0;
#pragma unroll
    for (int k = 0; k < 8; k++) {
        int idx = base + k;
        if (idx < NN) s += g_cnt_in[idx];
    }
    sred[t] = s;
    __syncthreads();
    for (int o = SCAN_BS / 2; o > 0; o >>= 1) {
        if (t < o) sred[t] += sred[t + o];
        __syncthreads();
    }
    if (t == 0) g_bsum[b] = sred[0];
}

// ---------------- scan pass 2 ----------------
__global__ __launch_bounds__(SCAN_BS) void k_scan_top() {
    __shared__ int s[SCAN_BS];
    int t = threadIdx.x;
    int v = (t < SCAN_NBLK) ? g_bsum[t] : 0;
    s[t] = v;
    __syncthreads();
    for (int o = 1; o < SCAN_BS; o <<= 1) {
        int u = (t >= o) ? s[t - o] : 0;
        __syncthreads();
        s[t] += u;
        __syncthreads();
    }
    if (t < SCAN_NBLK) g_bpref[t] = s[t] - v;
    if (t == 0) g_row_off[NN] = NE;
}

// ---------------- scan pass 3 (also computes g_ns) ----------------
__global__ __launch_bounds__(SCAN_BS) void k_scan_write() {
    __shared__ int sth[SCAN_BS];
    int b = blockIdx.x, t = threadIdx.x;
    int base = b * SCAN_ELEMS + t * 8;
    int vals[8];
    int s = 0;
#pragma unroll
    for (int k = 0; k < 8; k++) {
        int idx = base + k;
        vals[k] = (idx < NN) ? g_cnt_in[idx] : 0;
        s += vals[k];
    }
    sth[t] = s;
    __syncthreads();
    int incl = s;
    for (int o = 1; o < SCAN_BS; o <<= 1) {
        int u = (t >= o) ? sth[t - o] : 0;
        __syncthreads();
        incl += u;
        sth[t] = incl;
        __syncthreads();
    }
    int run = g_bpref[b] + incl - s;
#pragma unroll
    for (int k = 0; k < 8; k++) {
        int idx = base + k;
        if (idx < NN) {
            g_row_off[idx] = run;
            g_cursor[idx] = run;
            g_ns[idx] = rsqrtf(fmaxf((float)g_cnt_out[idx], 1.0f));
        }
        run += vals[k];
    }
}

// ---------------- CSR fill ----------------
__global__ void k_fill(const int* __restrict__ src, const int* __restrict__ dst) {
    int e = blockIdx.x * blockDim.x + threadIdx.x;
    if (e < NE) {
        int p = atomicAdd(&g_cursor[dst[e]], 1);
        g_csr_src[p] = src[e];
    }
}

// ---------------- gather embed + MLP1 + pool MLP ----------------
__global__ __launch_bounds__(256, 3) void k_h1(
    const int* __restrict__ tokens, const float* __restrict__ embed,
    const float* __restrict__ W1, const float* __restrict__ b1,
    const float* __restrict__ Wp, const float* __restrict__ bp)
{
    __shared__ __align__(16) u64 sW1[16 * 16], sWp[32 * 16];
    __shared__ u64 sb1[16], sbp[16];
    for (int t = threadIdx.x; t < 16 * 16; t += blockDim.x)
        ((float2*)sW1)[t] = ((const float2*)W1)[t];
    for (int t = threadIdx.x; t < 32 * 16; t += blockDim.x)
        ((float2*)sWp)[t] = ((const float2*)Wp)[t];
    for (int t = threadIdx.x; t < 16; t += blockDim.x) {
        ((float2*)sb1)[t] = ((const float2*)b1)[t];
        ((float2*)sbp)[t] = ((const float2*)bp)[t];
    }
    __syncthreads();

    int i = blockIdx.x * blockDim.x + threadIdx.x;
    if (i >= NN) return;

    int beg = g_row_off[i], end = g_row_off[i + 1];
    float4 a0 = make_float4(0, 0, 0, 0), a1 = a0, a2 = a0, a3 = a0;
    for (int e = beg; e < end; e++) {
        int s = g_csr_src[e];
        float ns = g_ns[s];
        const float4* er = (const float4*)(embed + (long)tokens[s] * 16);
        float4 v0 = er[0], v1 = er[1], v2 = er[2], v3 = er[3];
        a0.x += v0.x * ns; a0.y += v0.y * ns; a0.z += v0.z * ns; a0.w += v0.w * ns;
        a1.x += v1.x * ns; a1.y += v1.y * ns; a1.z += v1.z * ns; a1.w += v1.w * ns;
        a2.x += v2.x * ns; a2.y += v2.y * ns; a2.z += v2.z * ns; a2.w += v2.w * ns;
        a3.x += v3.x * ns; a3.y += v3.y * ns; a3.z += v3.z * ns; a3.w += v3.w * ns;
    }
    float nd = rsqrtf(fmaxf((float)(end - beg), 1.0f));
    float mr[16] = {a0.x * nd, a0.y * nd, a0.z * nd, a0.w * nd,
                    a1.x * nd, a1.y * nd, a1.z * nd, a1.w * nd,
                    a2.x * nd, a2.y * nd, a2.z * nd, a2.w * nd,
                    a3.x * nd, a3.y * nd, a3.z * nd, a3.w * nd};

    // h1 = relu(mr @ W1 + b1)
    u64 acc[16];
#pragma unroll
    for (int j = 0; j < 16; j++) acc[j] = sb1[j];
#pragma unroll
    for (int k = 0; k < 16; k++) {
        u64 av = pack2(mr[k]);
        const ulonglong2* pw = (const ulonglong2*)&sW1[k * 16];
#pragma unroll
        for (int jj = 0; jj < 8; jj++) {
            ulonglong2 w = pw[jj];
            fma2(acc[2 * jj], av, w.x);
            fma2(acc[2 * jj + 1], av, w.y);
        }
    }
    float h1f[32];
#pragma unroll
    for (int j = 0; j < 16; j++) {
        float2 f = unpack2(acc[j]);
        h1f[2 * j] = fmaxf(f.x, 0.f); h1f[2 * j + 1] = fmaxf(f.y, 0.f);
    }
#pragma unroll
    for (int k = 0; k < 8; k++)
        g_h1[i * 8 + k] = make_float4(h1f[4 * k], h1f[4 * k + 1], h1f[4 * k + 2], h1f[4 * k + 3]);

    // hp = relu(h1 @ Wpool + bpool)
    u64 pcc[16];
#pragma unroll
    for (int j = 0; j < 16; j++) pcc[j] = sbp[j];
#pragma unroll
    for (int k = 0; k < 32; k++) {
        u64 av = pack2(h1f[k]);
        const ulonglong2* pw = (const ulonglong2*)&sWp[k * 16];
#pragma unroll
        for (int jj = 0; jj < 8; jj++) {
            ulonglong2 w = pw[jj];
            fma2(pcc[2 * jj], av, w.x);
            fma2(pcc[2 * jj + 1], av, w.y);
        }
    }
#pragma unroll
    for (int j = 0; j < 8; j++) {
        float2 f0 = unpack2(pcc[2 * j]), f1 = unpack2(pcc[2 * j + 1]);
        g_hp[i * 8 + j] = make_float4(fmaxf(f0.x, 0.f), fmaxf(f0.y, 0.f),
                                      fmaxf(f1.x, 0.f), fmaxf(f1.y, 0.f));
    }
}

// ---------------- fused: gather-max + SAGE + lin + pooling ----------------
// Node-major staging: stag4[slot * 17 + j], j=0..15 (64 channels), stride 68
// words (68 mod 32 == 4 -> STS.128/LDS.128 and pooling reads all conflict-free).
// Gather: 1 node/thread. GEMMs: thread = 16 outputs (og) x 4 nodes (nt+64m),
// activations loaded 4-channels-at-a-time via LDS.128.
__global__ __launch_bounds__(256, 2) void k_out(
    const int* __restrict__ graph_ids,
    const float* __restrict__ Wself, const float* __restrict__ Wneigh,
    const float* __restrict__ bneigh,
    const float* __restrict__ Wlin, const float* __restrict__ blin,
    float* __restrict__ out)
{
    __shared__ __align__(16) u64 sWs[32 * 32], sWn[32 * 32], sWl[64 * 32];
    __shared__ u64 sbn[32], sbl[32];
    __shared__ int sgid[256];
    extern __shared__ __align__(16) float4 stag4[];   // 256 * SROW float4

    for (int t = threadIdx.x; t < 32 * 32; t += blockDim.x) {
        ((float2*)sWs)[t] = ((const float2*)Wself)[t];
        ((float2*)sWn)[t] = ((const float2*)Wneigh)[t];
    }
    for (int t = threadIdx.x; t < 64 * 32; t += blockDim.x)
        ((float2*)sWl)[t] = ((const float2*)Wlin)[t];
    for (int t = threadIdx.x; t < 32; t += blockDim.x) {
        ((float2*)sbn)[t] = ((const float2*)bneigh)[t];
        ((float2*)sbl)[t] = ((const float2*)blin)[t];
    }

    int tid = threadIdx.x;
    int i = blockIdx.x * 256 + tid;
    bool valid = i < NN;
    int ic = valid ? i : NN - 1;
    sgid[tid] = valid ? graph_ids[ic] : -1;

    // ---- gather phase: 1 node/thread, node-major row ----
#pragma unroll
    for (int k = 0; k < 8; k++)
        stag4[tid * SROW + k] = g_h1[(size_t)ic * 8 + k];
    {
        float hnf[32];
#pragma unroll
        for (int j = 0; j < 32; j++) hnf[j] = 0.f;
        int beg = g_row_off[ic], end = g_row_off[ic + 1];
        for (int e = beg; e < end; e++) {
            const float4* hr = &g_hp[(size_t)g_csr_src[e] * 8];
#pragma unroll
            for (int k = 0; k < 8; k++) {
                float4 v = hr[k];
                hnf[4 * k + 0] = fmaxf(hnf[4 * k + 0], v.x);
                hnf[4 * k + 1] = fmaxf(hnf[4 * k + 1], v.y);
                hnf[4 * k + 2] = fmaxf(hnf[4 * k + 2], v.z);
                hnf[4 * k + 3] = fmaxf(hnf[4 * k + 3], v.w);
            }
        }
#pragma unroll
        for (int j = 0; j < 8; j++)
            stag4[tid * SROW + 8 + j] =
                make_float4(hnf[4 * j], hnf[4 * j + 1], hnf[4 * j + 2], hnf[4 * j + 3]);
    }
    __syncthreads();

    int og = tid >> 6;   // output group: 16 outputs (8 pairs) starting at og*16
    int nt = tid & 63;   // node set {nt, nt+64, nt+128, nt+192}

    // ---- h2 = relu(af@Wself + hnf@Wneigh + bneigh) ----
    u64 acc[4][8];
#pragma unroll
    for (int m = 0; m < 4; m++)
#pragma unroll
        for (int p = 0; p < 8; p++) acc[m][p] = sbn[og * 8 + p];
#pragma unroll
    for (int kk = 0; kk < 8; kk++) {
        float4 a4[4], b4[4];
#pragma unroll
        for (int m = 0; m < 4; m++) {
            a4[m] = stag4[(nt + 64 * m) * SROW + kk];
            b4[m] = stag4[(nt + 64 * m) * SROW + 8 + kk];
        }
#pragma unroll
        for (int t = 0; t < 4; t++) {
            int k = 4 * kk + t;
            const ulonglong2* ps = (const ulonglong2*)&sWs[k * 32 + og * 8];
            const ulonglong2* pn = (const ulonglong2*)&sWn[k * 32 + og * 8];
            u64 a[4], b[4];
#pragma unroll
            for (int m = 0; m < 4; m++) {
                const float* ap = (const float*)&a4[m];
                const float* bp = (const float*)&b4[m];
                a[m] = pack2(ap[t]);
                b[m] = pack2(bp[t]);
            }
#pragma unroll
            for (int jj = 0; jj < 4; jj++) {
                ulonglong2 w = ps[jj];
                ulonglong2 u = pn[jj];
#pragma unroll
                for (int m = 0; m < 4; m++) {
                    fma2(acc[m][2 * jj], a[m], w.x);
                    fma2(acc[m][2 * jj + 1], a[m], w.y);
                    fma2(acc[m][2 * jj], b[m], u.x);
                    fma2(acc[m][2 * jj + 1], b[m], u.y);
                }
            }
        }
    }
    __syncthreads();   // all reads of channels 0..63 done before overwrite
#pragma unroll
    for (int m = 0; m < 4; m++)
#pragma unroll
        for (int j = 0; j < 4; j++) {
            float2 f0 = unpack2(acc[m][2 * j]);
            float2 f1 = unpack2(acc[m][2 * j + 1]);
            stag4[(nt + 64 * m) * SROW + og * 4 + j] =
                make_float4(fmaxf(f0.x, 0.f), fmaxf(f0.y, 0.f),
                            fmaxf(f1.x, 0.f), fmaxf(f1.y, 0.f));
        }
    __syncthreads();

    // ---- h3 = relu(h2@Wlin + blin) ----
    u64 a2[4][8];
#pragma unroll
    for (int m = 0; m < 4; m++)
#pragma unroll
        for (int p = 0; p < 8; p++) a2[m][p] = sbl[og * 8 + p];
#pragma unroll
    for (int kk = 0; kk < 16; kk++) {
        float4 a4[4];
#pragma unroll
        for (int m = 0; m < 4; m++)
            a4[m] = stag4[(nt + 64 * m) * SROW + kk];
#pragma unroll
        for (int t = 0; t < 4; t++) {
            int k2 = 4 * kk + t;
            const ulonglong2* pl = (const ulonglong2*)&sWl[k2 * 32 + og * 8];
            u64 a[4];
#pragma unroll
            for (int m = 0; m < 4; m++) {
                const float* ap = (const float*)&a4[m];
                a[m] = pack2(ap[t]);
            }
#pragma unroll
            for (int jj = 0; jj < 4; jj++) {
                ulonglong2 w = pl[jj];
#pragma unroll
                for (int m = 0; m < 4; m++) {
                    fma2(a2[m][2 * jj], a[m], w.x);
                    fma2(a2[m][2 * jj + 1], a[m], w.y);
                }
            }
        }
    }
    __syncthreads();
#pragma unroll
    for (int m = 0; m < 4; m++)
#pragma unroll
        for (int j = 0; j < 4; j++) {
            float2 f0 = unpack2(a2[m][2 * j]);
            float2 f1 = unpack2(a2[m][2 * j + 1]);
            stag4[(nt + 64 * m) * SROW + og * 4 + j] =
                make_float4(fmaxf(f0.x, 0.f), fmaxf(f0.y, 0.f),
                            fmaxf(f1.x, 0.f), fmaxf(f1.y, 0.f));
        }
    __syncthreads();

    // ---- pooling: run-based sum over this quarter's 64 slots ----
    {
        const float* stagf = (const float*)stag4;
        int c = tid & 63;    // channel
        int q = tid >> 6;    // quarter
        float run = 0.f;
        int cur = -1;
        for (int s = 0; s < 64; s++) {
            int slot = q * 64 + s;
            int g = sgid[slot];
            float v = stagf[slot * (SROW * 4) + c];
            if (g != cur) {
                if (cur >= 0) atomicAdd(out + cur * 64 + c, run);
                run = 0.f;
                cur = g;
            }
            if (g >= 0) run += v;
        }
        if (cur >= 0) atomicAdd(out + cur * 64 + c, run);
    }
}

// ---------------- launch ----------------
extern "C" void kernel_launch(void* const* d_in, const int* in_sizes, int n_in,
                              void* d_out, int out_size) {
    const int*   tokens    = (const int*)  d_in[0];
    const int*   edge_src  = (const int*)  d_in[1];
    const int*   edge_dst  = (const int*)  d_in[2];
    const int*   graph_ids = (const int*)  d_in[3];
    const float* embed     = (const float*)d_in[4];
    const float* W1        = (const float*)d_in[5];
    const float* b1        = (const float*)d_in[6];
    const float* Wpool     = (const float*)d_in[7];
    const float* bpool     = (const float*)d_in[8];
    const float* Wself     = (const float*)d_in[9];
    const float* Wneigh    = (const float*)d_in[10];
    const float* bneigh    = (const float*)d_in[11];
    const float* Wlin      = (const float*)d_in[12];
    const float* blin      = (const float*)d_in[13];
    float* out = (float*)d_out;

    cudaFuncSetAttribute(k_out, cudaFuncAttributeMaxDynamicSharedMemorySize, STAG_BYTES);

    const int TB = 256;
    int gridE = (NE + TB - 1) / TB;
    int gridN = (NN + TB - 1) / TB;
    int gridO = (NN + 255) / 256;

    k_init<<<gridN, TB>>>(out);
    k_deg<<<gridE, TB>>>(edge_src, edge_dst);
    k_scan_bsum <<<SCAN_NBLK, SCAN_BS>>>();
    k_scan_top  <<<1, SCAN_BS>>>();
    k_scan_write<<<SCAN_NBLK, SCAN_BS>>>();
    k_fill<<<gridE, TB>>>(edge_src, edge_dst);
    k_h1<<<gridN, TB>>>(tokens, embed, W1, b1, Wpool, bpool);
    k_out<<<gridO, TB, STAG_BYTES>>>(graph_ids, Wself, Wneigh, bneigh, Wlin, blin, out);
}